// round 1
// baseline (speedup 1.0000x reference)
#include <cuda_runtime.h>
#include <math.h>
#include <stdint.h>

// ---------------- problem constants ----------------
#define B_   64
#define T_   512
#define D_   128
#define S_   16
#define P_   3
#define H_   512
#define K_H  3
#define TOK_ 384
#define N_   510
#define MROWS (B_*N_)          // 32640
#define H3   (3*H_)            // 1536

// ---------------- device scratch ----------------
__device__ float g_aligned[B_*T_*D_];                 // 16.8 MB
__device__ float g_h[(size_t)MROWS*H_];               // 66.8 MB  (post-RMS h)
__device__ float g_gx[(size_t)MROWS*H3];              // 200 MB
__device__ float g_act[(size_t)MROWS*H3];             // 200 MB  (gelu(head1))
__device__ float g_hidden[(size_t)MROWS*H_];          // 66.8 MB
__device__ float g_hstateT[2][H_][B_];                // transposed GRU state, double buffered
__device__ unsigned g_bar_arrive;
__device__ unsigned g_bar_release;

// =====================================================================
// Generic tiled SGEMM:  C[M,N] = A[M,K] * B[N,K]^T + bias[N]   (row major)
// epi: 0 = none, 1 = exact GELU
// Batched mode (sidx != nullptr): blockIdx.z = batch b; A += b*strideAb,
// C += b*strideCb, s = sidx[b]; B += s*strideBsel; bias += s*strideBiasSel.
// Requires M%128==0, N%64==0, K%16==0 (true for all uses here).
// =====================================================================
#define BM 128
#define BN 64
#define BK 16

__global__ __launch_bounds__(256) void sgemm_kernel(
    const float* __restrict__ A, int lda,
    const float* __restrict__ Bm, int ldb,
    const float* __restrict__ bias,
    float* __restrict__ C, int ldc,
    int M, int N, int K, int epi,
    const int* __restrict__ sidx,
    size_t strideAb, size_t strideCb, size_t strideBsel, size_t strideBiasSel)
{
    __shared__ __align__(16) float As[BK][BM + 4];
    __shared__ __align__(16) float Bs[BK][BN + 4];

    if (sidx) {
        int bz = blockIdx.z;
        A    += (size_t)bz * strideAb;
        C    += (size_t)bz * strideCb;
        int s = __ldg(&sidx[bz]);
        Bm   += (size_t)s * strideBsel;
        bias += (size_t)s * strideBiasSel;
    }

    const int tid   = threadIdx.x;
    const int mBase = blockIdx.y * BM;
    const int nBase = blockIdx.x * BN;
    const int tm    = (tid / 16) * 8;   // 16 groups * 8 rows = 128
    const int tn    = (tid % 16) * 4;   // 16 groups * 4 cols = 64

    float acc[8][4];
#pragma unroll
    for (int i = 0; i < 8; i++)
#pragma unroll
        for (int j = 0; j < 4; j++) acc[i][j] = 0.f;

    for (int k0 = 0; k0 < K; k0 += BK) {
        // load A tile: 128x16 = 512 float4
#pragma unroll
        for (int it = 0; it < 2; it++) {
            int l  = tid + it * 256;
            int m  = l >> 2;
            int kq = (l & 3) * 4;
            float4 v = *(const float4*)(A + (size_t)(mBase + m) * lda + k0 + kq);
            As[kq + 0][m] = v.x; As[kq + 1][m] = v.y;
            As[kq + 2][m] = v.z; As[kq + 3][m] = v.w;
        }
        // load B tile: 64x16 = 256 float4
        {
            int l  = tid;
            int n  = l >> 2;
            int kq = (l & 3) * 4;
            float4 v = *(const float4*)(Bm + (size_t)(nBase + n) * ldb + k0 + kq);
            Bs[kq + 0][n] = v.x; Bs[kq + 1][n] = v.y;
            Bs[kq + 2][n] = v.z; Bs[kq + 3][n] = v.w;
        }
        __syncthreads();

#pragma unroll
        for (int kk = 0; kk < BK; kk++) {
            float4 a0 = *(const float4*)&As[kk][tm];
            float4 a1 = *(const float4*)&As[kk][tm + 4];
            float4 b0 = *(const float4*)&Bs[kk][tn];
            float av[8] = {a0.x, a0.y, a0.z, a0.w, a1.x, a1.y, a1.z, a1.w};
            float bv[4] = {b0.x, b0.y, b0.z, b0.w};
#pragma unroll
            for (int i = 0; i < 8; i++)
#pragma unroll
                for (int j = 0; j < 4; j++) acc[i][j] += av[i] * bv[j];
        }
        __syncthreads();
    }

    float bb[4];
#pragma unroll
    for (int j = 0; j < 4; j++) bb[j] = bias[nBase + tn + j];

#pragma unroll
    for (int i = 0; i < 8; i++) {
        float v0 = acc[i][0] + bb[0];
        float v1 = acc[i][1] + bb[1];
        float v2 = acc[i][2] + bb[2];
        float v3 = acc[i][3] + bb[3];
        if (epi == 1) {
            v0 = 0.5f * v0 * (1.0f + erff(v0 * 0.70710678118654752f));
            v1 = 0.5f * v1 * (1.0f + erff(v1 * 0.70710678118654752f));
            v2 = 0.5f * v2 * (1.0f + erff(v2 * 0.70710678118654752f));
            v3 = 0.5f * v3 * (1.0f + erff(v3 * 0.70710678118654752f));
        }
        *(float4*)(C + (size_t)(mBase + tm + i) * ldc + nBase + tn) =
            make_float4(v0, v1, v2, v3);
    }
}

// =====================================================================
// tokens[b,n,d*3+p] = aligned[b, n+p, d]  -> written into d_out tokens region
// =====================================================================
__global__ void tokens_kernel(float* __restrict__ out_tokens)
{
    int idx = blockIdx.x * blockDim.x + threadIdx.x;
    if (idx >= MROWS * TOK_) return;
    int t   = idx % TOK_;
    int row = idx / TOK_;
    int n   = row % N_;
    int b   = row / N_;
    int d   = t / P_;
    int p   = t % P_;
    out_tokens[idx] = g_aligned[((size_t)(b * T_ + n + p)) * D_ + d];
}

// =====================================================================
// RMS norm in place on g_h rows: h = h / sqrt(mean(h^2)+eps) * scale
// =====================================================================
__global__ __launch_bounds__(128) void rms_kernel(const float* __restrict__ scale)
{
    int row = blockIdx.x;
    float* h = g_h + (size_t)row * H_;
    int tid = threadIdx.x;

    float4 x = *(float4*)(h + tid * 4);
    float ss = x.x * x.x + x.y * x.y + x.z * x.z + x.w * x.w;
#pragma unroll
    for (int o = 16; o; o >>= 1) ss += __shfl_xor_sync(0xffffffffu, ss, o);

    __shared__ float wsum[4];
    if ((tid & 31) == 0) wsum[tid >> 5] = ss;
    __syncthreads();
    float tot = wsum[0] + wsum[1] + wsum[2] + wsum[3];
    float inv = rsqrtf(tot * (1.0f / H_) + 1e-6f);

    float4 sc = *(const float4*)(scale + tid * 4);
    x.x *= inv * sc.x; x.y *= inv * sc.y; x.z *= inv * sc.z; x.w *= inv * sc.w;
    *(float4*)(h + tid * 4) = x;
}

// =====================================================================
// GRU: persistent kernel. 128 blocks, each owns 4 hidden columns.
// Weights for its 12 rows (3 gates x 4 cols) cached k-major in smem.
// Hidden state kept transposed (h[k][b]) in global, double buffered;
// global sense barrier between steps (all 128 blocks co-resident).
// 256 threads: tid -> (b = tid&63, kq = tid>>6), k-range = [kq*128, +128).
// =====================================================================
#define GRU_BLOCKS 128
#define CPB 4

__device__ __forceinline__ void grid_barrier(unsigned gen)
{
    __syncthreads();
    if (threadIdx.x == 0) {
        __threadfence();
        unsigned a = atomicAdd(&g_bar_arrive, 1u);
        if (a == gen * GRU_BLOCKS + (GRU_BLOCKS - 1)) {
            atomicAdd(&g_bar_release, 1u);
        } else {
            while (true) {
                unsigned r = *(volatile unsigned*)&g_bar_release;
                if (r > gen) break;
                __nanosleep(64);
            }
        }
        __threadfence();
    }
    __syncthreads();
}

__global__ void gru_init_kernel()
{
    int idx = blockIdx.x * blockDim.x + threadIdx.x;
    float* p = &g_hstateT[0][0][0];
    if (idx < 2 * H_ * B_) p[idx] = 0.f;
    if (idx == 0) { g_bar_arrive = 0u; g_bar_release = 0u; }
}

__global__ __launch_bounds__(256, 1) void gru_kernel(
    const float* __restrict__ Whh, const float* __restrict__ bhh)
{
    __shared__ __align__(16) float ws[H_][12];   // ws[k][g*4+c]
    __shared__ float red[3][B_][12];
    __shared__ float sbhh[12];

    const int bid  = blockIdx.x;
    const int col0 = bid * CPB;
    const int tid  = threadIdx.x;

    for (int i = tid; i < H_ * 12; i += 256) {
        int k = i / 12, j = i % 12;
        int g = j >> 2, c = j & 3;
        ws[k][j] = Whh[(size_t)(g * H_ + col0 + c) * H_ + k];
    }
    if (tid < 12) {
        int g = tid >> 2, c = tid & 3;
        sbhh[tid] = bhh[g * H_ + col0 + c];
    }
    __syncthreads();

    const int b  = tid & 63;
    const int kq = tid >> 6;       // 0..3
    const int kb = kq * 128;
    int cur = 0;

    for (int n = 0; n < N_; n++) {
        float acc[12];
#pragma unroll
        for (int j = 0; j < 12; j++) acc[j] = 0.f;

        const float* hT = &g_hstateT[cur][0][0];
#pragma unroll 4
        for (int k = kb; k < kb + 128; k++) {
            float hv = __ldcg(hT + k * B_ + b);
            float4 w0 = *(const float4*)&ws[k][0];
            float4 w1 = *(const float4*)&ws[k][4];
            float4 w2 = *(const float4*)&ws[k][8];
            acc[0] += hv * w0.x; acc[1] += hv * w0.y; acc[2]  += hv * w0.z; acc[3]  += hv * w0.w;
            acc[4] += hv * w1.x; acc[5] += hv * w1.y; acc[6]  += hv * w1.z; acc[7]  += hv * w1.w;
            acc[8] += hv * w2.x; acc[9] += hv * w2.y; acc[10] += hv * w2.z; acc[11] += hv * w2.w;
        }

        if (kq) {
#pragma unroll
            for (int j = 0; j < 12; j++) red[kq - 1][b][j] = acc[j];
        }
        __syncthreads();

        if (kq == 0) {
            const float* gx = g_gx + ((size_t)(b * N_ + n)) * H3;
            float hn[4];
#pragma unroll
            for (int c = 0; c < 4; c++) {
                float ghr = acc[c]     + red[0][b][c]     + red[1][b][c]     + red[2][b][c]     + sbhh[c];
                float ghz = acc[4 + c] + red[0][b][4 + c] + red[1][b][4 + c] + red[2][b][4 + c] + sbhh[4 + c];
                float ghn = acc[8 + c] + red[0][b][8 + c] + red[1][b][8 + c] + red[2][b][8 + c] + sbhh[8 + c];
                float gxr = __ldg(gx + col0 + c);
                float gxz = __ldg(gx + H_ + col0 + c);
                float gxn = __ldg(gx + 2 * H_ + col0 + c);
                float r = 1.0f / (1.0f + expf(-(gxr + ghr)));
                float z = 1.0f / (1.0f + expf(-(gxz + ghz)));
                float nn = tanhf(gxn + r * ghn);
                float hp = __ldcg(&g_hstateT[cur][col0 + c][b]);
                hn[c] = (1.0f - z) * nn + z * hp;
                g_hstateT[cur ^ 1][col0 + c][b] = hn[c];
            }
            *(float4*)(g_hidden + ((size_t)(b * N_ + n)) * H_ + col0) =
                make_float4(hn[0], hn[1], hn[2], hn[3]);
        }

        grid_barrier((unsigned)n);
        cur ^= 1;
    }
}

// =====================================================================
// host side
// =====================================================================
extern "C" void kernel_launch(void* const* d_in, const int* in_sizes, int n_in,
                              void* d_out, int out_size)
{
    const float* x      = (const float*)d_in[0];
    const int*   sidx   = (const int*)  d_in[1];
    const float* sW     = (const float*)d_in[2];
    const float* sb     = (const float*)d_in[3];
    const float* projW  = (const float*)d_in[4];
    const float* projb  = (const float*)d_in[5];
    const float* rscale = (const float*)d_in[6];
    const float* Wih    = (const float*)d_in[7];
    const float* Whh    = (const float*)d_in[8];
    const float* bih    = (const float*)d_in[9];
    const float* bhh    = (const float*)d_in[10];
    const float* W1     = (const float*)d_in[11];
    const float* b1     = (const float*)d_in[12];
    const float* W2     = (const float*)d_in[13];
    const float* b2     = (const float*)d_in[14];

    float* out        = (float*)d_out;
    float* out_preds  = out;
    float* out_tokens = out + (size_t)K_H * MROWS * TOK_;

    float *pAligned, *pH, *pGx, *pAct, *pHidden;
    cudaGetSymbolAddress((void**)&pAligned, g_aligned);
    cudaGetSymbolAddress((void**)&pH,       g_h);
    cudaGetSymbolAddress((void**)&pGx,      g_gx);
    cudaGetSymbolAddress((void**)&pAct,     g_act);
    cudaGetSymbolAddress((void**)&pHidden,  g_hidden);

    // 1) session alignment: per-batch GEMM [512x128] = x[b] @ W[s]^T + b[s]
    sgemm_kernel<<<dim3(D_ / BN, T_ / BM, B_), 256>>>(
        x, D_, sW, D_, sb, pAligned, D_,
        T_, D_, D_, 0,
        sidx, (size_t)T_ * D_, (size_t)T_ * D_, (size_t)D_ * D_, (size_t)D_);

    // 2) tokens gather (also the second output)
    tokens_kernel<<<(MROWS * TOK_ + 255) / 256, 256>>>(out_tokens);

    // 3) proj: h = tokens @ projW^T + projb
    sgemm_kernel<<<dim3(H_ / BN, MROWS / BM), 256>>>(
        out_tokens, TOK_, projW, TOK_, projb, pH, H_,
        MROWS, H_, TOK_, 0, nullptr, 0, 0, 0, 0);

    // 4) RMS norm in place
    rms_kernel<<<MROWS, 128>>>(rscale);

    // 5) gx = h @ Wih^T + bih
    sgemm_kernel<<<dim3(H3 / BN, MROWS / BM), 256>>>(
        pH, H_, Wih, H_, bih, pGx, H3,
        MROWS, H3, H_, 0, nullptr, 0, 0, 0, 0);

    // 6) GRU recurrence
    gru_init_kernel<<<(2 * H_ * B_ + 255) / 256, 256>>>();
    gru_kernel<<<GRU_BLOCKS, 256>>>(Whh, bhh);

    // 7) head1 (all 3 horizons fused as N=1536) + exact GELU
    sgemm_kernel<<<dim3(H3 / BN, MROWS / BM), 256>>>(
        pHidden, H_, W1, H_, b1, pAct, H3,
        MROWS, H3, H_, 1, nullptr, 0, 0, 0, 0);

    // 8) head2 per horizon -> preds
    for (int k = 0; k < K_H; k++) {
        sgemm_kernel<<<dim3(TOK_ / BN, MROWS / BM), 256>>>(
            pAct + (size_t)k * H_, H3,
            W2 + (size_t)k * TOK_ * H_, H_,
            b2 + (size_t)k * TOK_,
            out_preds + (size_t)k * MROWS * TOK_, TOK_,
            MROWS, TOK_, H_, 0, nullptr, 0, 0, 0, 0);
    }
}

// round 2
// speedup vs baseline: 1.2541x; 1.2541x over previous
#include <cuda_runtime.h>
#include <math.h>
#include <stdint.h>

// ---------------- problem constants ----------------
#define B_   64
#define T_   512
#define D_   128
#define S_   16
#define P_   3
#define H_   512
#define K_H  3
#define TOK_ 384
#define N_   510
#define MROWS (B_*N_)          // 32640
#define H3   (3*H_)            // 1536

// ---------------- device scratch ----------------
__device__ float g_aligned[B_*T_*D_];                 // 16.8 MB
__device__ float g_h[(size_t)MROWS*H_];               // 66.8 MB  (post-RMS h)
__device__ float g_gx[(size_t)MROWS*H3];              // 200 MB
__device__ float g_act[(size_t)MROWS*H3];             // 200 MB  (gelu(head1))
__device__ float g_hidden[(size_t)MROWS*H_];          // 66.8 MB
__device__ float g_hstateT[2][H_][B_];                // transposed GRU state, double buffered
__device__ unsigned g_bar_arrive;
__device__ unsigned g_bar_release;

// =====================================================================
// fp32 tiled SGEMM (kept ONLY for the session-align step, which feeds the
// `tokens` output directly — keeps that output at fp32 accuracy).
// C[M,N] = A[M,K] * B[N,K]^T + bias[N], batched via sidx.
// =====================================================================
#define BM 128
#define BN 64
#define BK 16

__global__ __launch_bounds__(256) void sgemm_kernel(
    const float* __restrict__ A, int lda,
    const float* __restrict__ Bm, int ldb,
    const float* __restrict__ bias,
    float* __restrict__ C, int ldc,
    int M, int N, int K,
    const int* __restrict__ sidx,
    size_t strideAb, size_t strideCb, size_t strideBsel, size_t strideBiasSel)
{
    __shared__ __align__(16) float As[BK][BM + 4];
    __shared__ __align__(16) float Bs[BK][BN + 4];

    if (sidx) {
        int bz = blockIdx.z;
        A    += (size_t)bz * strideAb;
        C    += (size_t)bz * strideCb;
        int s = __ldg(&sidx[bz]);
        Bm   += (size_t)s * strideBsel;
        bias += (size_t)s * strideBiasSel;
    }

    const int tid   = threadIdx.x;
    const int mBase = blockIdx.y * BM;
    const int nBase = blockIdx.x * BN;
    const int tm    = (tid / 16) * 8;
    const int tn    = (tid % 16) * 4;

    float acc[8][4];
#pragma unroll
    for (int i = 0; i < 8; i++)
#pragma unroll
        for (int j = 0; j < 4; j++) acc[i][j] = 0.f;

    for (int k0 = 0; k0 < K; k0 += BK) {
#pragma unroll
        for (int it = 0; it < 2; it++) {
            int l  = tid + it * 256;
            int m  = l >> 2;
            int kq = (l & 3) * 4;
            float4 v = *(const float4*)(A + (size_t)(mBase + m) * lda + k0 + kq);
            As[kq + 0][m] = v.x; As[kq + 1][m] = v.y;
            As[kq + 2][m] = v.z; As[kq + 3][m] = v.w;
        }
        {
            int l  = tid;
            int n  = l >> 2;
            int kq = (l & 3) * 4;
            float4 v = *(const float4*)(Bm + (size_t)(nBase + n) * ldb + k0 + kq);
            Bs[kq + 0][n] = v.x; Bs[kq + 1][n] = v.y;
            Bs[kq + 2][n] = v.z; Bs[kq + 3][n] = v.w;
        }
        __syncthreads();

#pragma unroll
        for (int kk = 0; kk < BK; kk++) {
            float4 a0 = *(const float4*)&As[kk][tm];
            float4 a1 = *(const float4*)&As[kk][tm + 4];
            float4 b0 = *(const float4*)&Bs[kk][tn];
            float av[8] = {a0.x, a0.y, a0.z, a0.w, a1.x, a1.y, a1.z, a1.w};
            float bv[4] = {b0.x, b0.y, b0.z, b0.w};
#pragma unroll
            for (int i = 0; i < 8; i++)
#pragma unroll
                for (int j = 0; j < 4; j++) acc[i][j] += av[i] * bv[j];
        }
        __syncthreads();
    }

    float bb[4];
#pragma unroll
    for (int j = 0; j < 4; j++) bb[j] = bias[nBase + tn + j];

#pragma unroll
    for (int i = 0; i < 8; i++) {
        *(float4*)(C + (size_t)(mBase + tm + i) * ldc + nBase + tn) =
            make_float4(acc[i][0] + bb[0], acc[i][1] + bb[1],
                        acc[i][2] + bb[2], acc[i][3] + bb[3]);
    }
}

// =====================================================================
// TF32 tensor-core GEMM: C[M,N] = A[M,K] * W[N,K]^T + bias[N]
// Block tile 128x128x32, 8 warps (2x4), warp tile 64x32 (4x4 m16n8k8 tiles).
// Smem rows padded to 36 floats -> fragment LDS bank = (4g+t), conflict-free.
// cp.async double-buffered staging; cvt.rna.tf32 at fragment load.
// Requires M%128==0, N%128==0, K%32==0 (true for all uses).
// epi: 0 = bias only, 1 = bias + exact GELU
// =====================================================================
#define TPAD  36
#define ATILE (128*TPAD)

__device__ __forceinline__ uint32_t f2tf(float x)
{
    uint32_t r;
    asm("cvt.rna.tf32.f32 %0, %1;" : "=r"(r) : "f"(x));
    return r;
}

__device__ __forceinline__ void mma_tf32(float* c, const uint32_t* a, const uint32_t* b)
{
    asm volatile(
        "mma.sync.aligned.m16n8k8.row.col.f32.tf32.tf32.f32 "
        "{%0,%1,%2,%3}, {%4,%5,%6,%7}, {%8,%9}, {%0,%1,%2,%3};"
        : "+f"(c[0]), "+f"(c[1]), "+f"(c[2]), "+f"(c[3])
        : "r"(a[0]), "r"(a[1]), "r"(a[2]), "r"(a[3]), "r"(b[0]), "r"(b[1]));
}

__global__ __launch_bounds__(256, 2) void tgemm_kernel(
    const float* __restrict__ A, int lda,
    const float* __restrict__ Bw, int ldb,
    const float* __restrict__ bias,
    float* __restrict__ C, int ldc,
    int K, int epi)
{
    extern __shared__ float smem[];
    float* AsBuf[2] = { smem,             smem + ATILE };
    float* BsBuf[2] = { smem + 2*ATILE,   smem + 3*ATILE };

    const int tid   = threadIdx.x;
    const int mBase = blockIdx.y << 7;
    const int nBase = blockIdx.x << 7;

    const int lane = tid & 31;
    const int warp = tid >> 5;
    const int g = lane >> 2;
    const int t = lane & 3;
    const int wm = (warp & 1) << 6;   // 0 / 64
    const int wn = (warp >> 1) << 5;  // 0 / 32 / 64 / 96

    float acc[4][4][4];
#pragma unroll
    for (int mt = 0; mt < 4; mt++)
#pragma unroll
        for (int nt = 0; nt < 4; nt++)
#pragma unroll
            for (int c = 0; c < 4; c++) acc[mt][nt][c] = 0.f;

#define STAGE(dstA, dstB, kk0)                                                   \
    do {                                                                         \
        _Pragma("unroll")                                                        \
        for (int i_ = 0; i_ < 4; i_++) {                                         \
            int l_  = tid + (i_ << 8);                                           \
            int m_  = l_ >> 3;                                                   \
            int kq_ = (l_ & 7) << 2;                                             \
            uint32_t sa_ = (uint32_t)__cvta_generic_to_shared((dstA) + m_*TPAD + kq_); \
            const float* ga_ = A + (size_t)(mBase + m_) * lda + (kk0) + kq_;     \
            asm volatile("cp.async.cg.shared.global [%0], [%1], 16;"             \
                         :: "r"(sa_), "l"(ga_));                                 \
            uint32_t sb_ = (uint32_t)__cvta_generic_to_shared((dstB) + m_*TPAD + kq_); \
            const float* gb_ = Bw + (size_t)(nBase + m_) * ldb + (kk0) + kq_;    \
            asm volatile("cp.async.cg.shared.global [%0], [%1], 16;"             \
                         :: "r"(sb_), "l"(gb_));                                 \
        }                                                                        \
    } while (0)

    const int ntiles = K >> 5;
    STAGE(AsBuf[0], BsBuf[0], 0);
    asm volatile("cp.async.commit_group;");

    int bf = 0;
    for (int kt = 0; kt < ntiles; kt++) {
        if (kt + 1 < ntiles) STAGE(AsBuf[bf ^ 1], BsBuf[bf ^ 1], (kt + 1) << 5);
        asm volatile("cp.async.commit_group;");
        asm volatile("cp.async.wait_group 1;");
        __syncthreads();

        const float* Asb = AsBuf[bf];
        const float* Bsb = BsBuf[bf];
#pragma unroll
        for (int ks = 0; ks < 4; ks++) {
            const int k0 = ks << 3;
            uint32_t af[4][4], bfr[4][2];
#pragma unroll
            for (int mt = 0; mt < 4; mt++) {
                const float* p = Asb + (wm + mt*16 + g) * TPAD + k0 + t;
                af[mt][0] = f2tf(p[0]);
                af[mt][1] = f2tf(p[8*TPAD]);
                af[mt][2] = f2tf(p[4]);
                af[mt][3] = f2tf(p[8*TPAD + 4]);
            }
#pragma unroll
            for (int nt = 0; nt < 4; nt++) {
                const float* p = Bsb + (wn + nt*8 + g) * TPAD + k0 + t;
                bfr[nt][0] = f2tf(p[0]);
                bfr[nt][1] = f2tf(p[4]);
            }
#pragma unroll
            for (int mt = 0; mt < 4; mt++)
#pragma unroll
                for (int nt = 0; nt < 4; nt++)
                    mma_tf32(acc[mt][nt], af[mt], bfr[nt]);
        }
        bf ^= 1;
        __syncthreads();
    }
#undef STAGE

    // epilogue
#pragma unroll
    for (int mt = 0; mt < 4; mt++) {
        int r0 = mBase + wm + mt*16 + g;
#pragma unroll
        for (int nt = 0; nt < 4; nt++) {
            int c0 = nBase + wn + nt*8 + 2*t;
            float b0 = __ldg(bias + c0);
            float b1 = __ldg(bias + c0 + 1);
            float v00 = acc[mt][nt][0] + b0;
            float v01 = acc[mt][nt][1] + b1;
            float v10 = acc[mt][nt][2] + b0;
            float v11 = acc[mt][nt][3] + b1;
            if (epi == 1) {
                v00 = 0.5f * v00 * (1.0f + erff(v00 * 0.70710678118654752f));
                v01 = 0.5f * v01 * (1.0f + erff(v01 * 0.70710678118654752f));
                v10 = 0.5f * v10 * (1.0f + erff(v10 * 0.70710678118654752f));
                v11 = 0.5f * v11 * (1.0f + erff(v11 * 0.70710678118654752f));
            }
            *(float2*)(C + (size_t)r0 * ldc + c0)       = make_float2(v00, v01);
            *(float2*)(C + (size_t)(r0 + 8) * ldc + c0) = make_float2(v10, v11);
        }
    }
}

// =====================================================================
// tokens[b,n,d*3+p] = aligned[b, n+p, d]
// =====================================================================
__global__ void tokens_kernel(float* __restrict__ out_tokens)
{
    int idx = blockIdx.x * blockDim.x + threadIdx.x;
    if (idx >= MROWS * TOK_) return;
    int t   = idx % TOK_;
    int row = idx / TOK_;
    int n   = row % N_;
    int b   = row / N_;
    int d   = t / P_;
    int p   = t % P_;
    out_tokens[idx] = g_aligned[((size_t)(b * T_ + n + p)) * D_ + d];
}

// =====================================================================
// RMS norm in place on g_h rows
// =====================================================================
__global__ __launch_bounds__(128) void rms_kernel(const float* __restrict__ scale)
{
    int row = blockIdx.x;
    float* h = g_h + (size_t)row * H_;
    int tid = threadIdx.x;

    float4 x = *(float4*)(h + tid * 4);
    float ss = x.x * x.x + x.y * x.y + x.z * x.z + x.w * x.w;
#pragma unroll
    for (int o = 16; o; o >>= 1) ss += __shfl_xor_sync(0xffffffffu, ss, o);

    __shared__ float wsum[4];
    if ((tid & 31) == 0) wsum[tid >> 5] = ss;
    __syncthreads();
    float tot = wsum[0] + wsum[1] + wsum[2] + wsum[3];
    float inv = rsqrtf(tot * (1.0f / H_) + 1e-6f);

    float4 sc = *(const float4*)(scale + tid * 4);
    x.x *= inv * sc.x; x.y *= inv * sc.y; x.z *= inv * sc.z; x.w *= inv * sc.w;
    *(float4*)(h + tid * 4) = x;
}

// =====================================================================
// GRU: persistent kernel (unchanged from R1)
// =====================================================================
#define GRU_BLOCKS 128
#define CPB 4

__device__ __forceinline__ void grid_barrier(unsigned gen)
{
    __syncthreads();
    if (threadIdx.x == 0) {
        __threadfence();
        unsigned a = atomicAdd(&g_bar_arrive, 1u);
        if (a == gen * GRU_BLOCKS + (GRU_BLOCKS - 1)) {
            atomicAdd(&g_bar_release, 1u);
        } else {
            while (true) {
                unsigned r = *(volatile unsigned*)&g_bar_release;
                if (r > gen) break;
                __nanosleep(64);
            }
        }
        __threadfence();
    }
    __syncthreads();
}

__global__ void gru_init_kernel()
{
    int idx = blockIdx.x * blockDim.x + threadIdx.x;
    float* p = &g_hstateT[0][0][0];
    if (idx < 2 * H_ * B_) p[idx] = 0.f;
    if (idx == 0) { g_bar_arrive = 0u; g_bar_release = 0u; }
}

__global__ __launch_bounds__(256, 1) void gru_kernel(
    const float* __restrict__ Whh, const float* __restrict__ bhh)
{
    __shared__ __align__(16) float ws[H_][12];
    __shared__ float red[3][B_][12];
    __shared__ float sbhh[12];

    const int bid  = blockIdx.x;
    const int col0 = bid * CPB;
    const int tid  = threadIdx.x;

    for (int i = tid; i < H_ * 12; i += 256) {
        int k = i / 12, j = i % 12;
        int gg = j >> 2, c = j & 3;
        ws[k][j] = Whh[(size_t)(gg * H_ + col0 + c) * H_ + k];
    }
    if (tid < 12) {
        int gg = tid >> 2, c = tid & 3;
        sbhh[tid] = bhh[gg * H_ + col0 + c];
    }
    __syncthreads();

    const int b  = tid & 63;
    const int kq = tid >> 6;
    const int kb = kq * 128;
    int cur = 0;

    for (int n = 0; n < N_; n++) {
        float acc[12];
#pragma unroll
        for (int j = 0; j < 12; j++) acc[j] = 0.f;

        const float* hT = &g_hstateT[cur][0][0];
#pragma unroll 4
        for (int k = kb; k < kb + 128; k++) {
            float hv = __ldcg(hT + k * B_ + b);
            float4 w0 = *(const float4*)&ws[k][0];
            float4 w1 = *(const float4*)&ws[k][4];
            float4 w2 = *(const float4*)&ws[k][8];
            acc[0] += hv * w0.x; acc[1] += hv * w0.y; acc[2]  += hv * w0.z; acc[3]  += hv * w0.w;
            acc[4] += hv * w1.x; acc[5] += hv * w1.y; acc[6]  += hv * w1.z; acc[7]  += hv * w1.w;
            acc[8] += hv * w2.x; acc[9] += hv * w2.y; acc[10] += hv * w2.z; acc[11] += hv * w2.w;
        }

        if (kq) {
#pragma unroll
            for (int j = 0; j < 12; j++) red[kq - 1][b][j] = acc[j];
        }
        __syncthreads();

        if (kq == 0) {
            const float* gx = g_gx + ((size_t)(b * N_ + n)) * H3;
            float hn[4];
#pragma unroll
            for (int c = 0; c < 4; c++) {
                float ghr = acc[c]     + red[0][b][c]     + red[1][b][c]     + red[2][b][c]     + sbhh[c];
                float ghz = acc[4 + c] + red[0][b][4 + c] + red[1][b][4 + c] + red[2][b][4 + c] + sbhh[4 + c];
                float ghn = acc[8 + c] + red[0][b][8 + c] + red[1][b][8 + c] + red[2][b][8 + c] + sbhh[8 + c];
                float gxr = __ldg(gx + col0 + c);
                float gxz = __ldg(gx + H_ + col0 + c);
                float gxn = __ldg(gx + 2 * H_ + col0 + c);
                float r = 1.0f / (1.0f + expf(-(gxr + ghr)));
                float z = 1.0f / (1.0f + expf(-(gxz + ghz)));
                float nn = tanhf(gxn + r * ghn);
                float hp = __ldcg(&g_hstateT[cur][col0 + c][b]);
                hn[c] = (1.0f - z) * nn + z * hp;
                g_hstateT[cur ^ 1][col0 + c][b] = hn[c];
            }
            *(float4*)(g_hidden + ((size_t)(b * N_ + n)) * H_ + col0) =
                make_float4(hn[0], hn[1], hn[2], hn[3]);
        }

        grid_barrier((unsigned)n);
        cur ^= 1;
    }
}

// =====================================================================
// host side
// =====================================================================
extern "C" void kernel_launch(void* const* d_in, const int* in_sizes, int n_in,
                              void* d_out, int out_size)
{
    const float* x      = (const float*)d_in[0];
    const int*   sidx   = (const int*)  d_in[1];
    const float* sW     = (const float*)d_in[2];
    const float* sb     = (const float*)d_in[3];
    const float* projW  = (const float*)d_in[4];
    const float* projb  = (const float*)d_in[5];
    const float* rscale = (const float*)d_in[6];
    const float* Wih    = (const float*)d_in[7];
    const float* Whh    = (const float*)d_in[8];
    const float* bih    = (const float*)d_in[9];
    const float* bhh    = (const float*)d_in[10];
    const float* W1     = (const float*)d_in[11];
    const float* b1     = (const float*)d_in[12];
    const float* W2     = (const float*)d_in[13];
    const float* b2     = (const float*)d_in[14];

    float* out        = (float*)d_out;
    float* out_preds  = out;
    float* out_tokens = out + (size_t)K_H * MROWS * TOK_;

    float *pAligned, *pH, *pGx, *pAct, *pHidden;
    cudaGetSymbolAddress((void**)&pAligned, g_aligned);
    cudaGetSymbolAddress((void**)&pH,       g_h);
    cudaGetSymbolAddress((void**)&pGx,      g_gx);
    cudaGetSymbolAddress((void**)&pAct,     g_act);
    cudaGetSymbolAddress((void**)&pHidden,  g_hidden);

    static int smem_set = 0;
    if (!smem_set) {
        cudaFuncSetAttribute(tgemm_kernel,
                             cudaFuncAttributeMaxDynamicSharedMemorySize,
                             4 * ATILE * (int)sizeof(float));
        smem_set = 1;
    }
    const int dynsmem = 4 * ATILE * (int)sizeof(float);  // 73728 B

    // 1) session alignment (fp32 — feeds the tokens output directly)
    sgemm_kernel<<<dim3(D_ / BN, T_ / BM, B_), 256>>>(
        x, D_, sW, D_, sb, pAligned, D_,
        T_, D_, D_,
        sidx, (size_t)T_ * D_, (size_t)T_ * D_, (size_t)D_ * D_, (size_t)D_);

    // 2) tokens gather (second output)
    tokens_kernel<<<(MROWS * TOK_ + 255) / 256, 256>>>(out_tokens);

    // 3) proj: h = tokens @ projW^T + projb   (tf32)
    tgemm_kernel<<<dim3(H_ / 128, MROWS / 128), 256, dynsmem>>>(
        out_tokens, TOK_, projW, TOK_, projb, pH, H_, TOK_, 0);

    // 4) RMS norm in place
    rms_kernel<<<MROWS, 128>>>(rscale);

    // 5) gx = h @ Wih^T + bih   (tf32)
    tgemm_kernel<<<dim3(H3 / 128, MROWS / 128), 256, dynsmem>>>(
        pH, H_, Wih, H_, bih, pGx, H3, H_, 0);

    // 6) GRU recurrence
    gru_init_kernel<<<(2 * H_ * B_ + 255) / 256, 256>>>();
    gru_kernel<<<GRU_BLOCKS, 256>>>(Whh, bhh);

    // 7) head1 (3 horizons fused as N=1536) + exact GELU   (tf32)
    tgemm_kernel<<<dim3(H3 / 128, MROWS / 128), 256, dynsmem>>>(
        pHidden, H_, W1, H_, b1, pAct, H3, H_, 1);

    // 8) head2 per horizon -> preds   (tf32)
    for (int k = 0; k < K_H; k++) {
        tgemm_kernel<<<dim3(TOK_ / 128, MROWS / 128), 256, dynsmem>>>(
            pAct + (size_t)k * H_, H3,
            W2 + (size_t)k * TOK_ * H_, H_,
            b2 + (size_t)k * TOK_,
            out_preds + (size_t)k * MROWS * TOK_, TOK_, H_, 0);
    }
}

// round 4
// speedup vs baseline: 1.2563x; 1.0017x over previous
#include <cuda_runtime.h>
#include <cuda_bf16.h>
#include <math.h>
#include <stdint.h>

// ---------------- problem constants ----------------
#define B_   64
#define T_   512
#define D_   128
#define P_   3
#define H_   512
#define K_H  3
#define TOK_ 384
#define N_   510
#define MROWS (B_*N_)          // 32640
#define H3   (3*H_)            // 1536

// ---------------- device scratch ----------------
__device__ float g_aligned[B_*T_*D_];
__device__ float g_h[(size_t)MROWS*H_];
__device__ float g_gx[(size_t)MROWS*H3];
__device__ float g_hidden[(size_t)MROWS*H_];
__device__ float g_hstateT[2][H_][B_];
__device__ unsigned g_bar_arrive;
__device__ unsigned g_bar_release;

// bf16 hi/lo split buffers
__device__ __nv_bfloat16 g_tokHi[(size_t)MROWS*TOK_];
__device__ __nv_bfloat16 g_tokLo[(size_t)MROWS*TOK_];
__device__ __nv_bfloat16 g_hHi[(size_t)MROWS*H_];
__device__ __nv_bfloat16 g_hLo[(size_t)MROWS*H_];
__device__ __nv_bfloat16 g_hidHi[(size_t)MROWS*H_];
__device__ __nv_bfloat16 g_hidLo[(size_t)MROWS*H_];
__device__ __nv_bfloat16 g_actHi[(size_t)MROWS*H3];
__device__ __nv_bfloat16 g_actLo[(size_t)MROWS*H3];
__device__ __nv_bfloat16 g_pwHi[H_*TOK_],  g_pwLo[H_*TOK_];
__device__ __nv_bfloat16 g_wihHi[H3*H_],   g_wihLo[H3*H_];
__device__ __nv_bfloat16 g_w1Hi[H3*H_],    g_w1Lo[H3*H_];
__device__ __nv_bfloat16 g_w2Hi[K_H*TOK_*H_], g_w2Lo[K_H*TOK_*H_];

// =====================================================================
// helpers
// =====================================================================
__device__ __forceinline__ uint32_t smem_u32(const void* p)
{
    uint32_t a;
    asm("{ .reg .u64 t; cvta.to.shared.u64 t, %1; cvt.u32.u64 %0, t; }"
        : "=r"(a) : "l"(p));
    return a;
}

__device__ __forceinline__ void ldsm4(uint32_t* r, uint32_t addr)
{
    asm volatile("ldmatrix.sync.aligned.m8n8.x4.shared.b16 {%0,%1,%2,%3}, [%4];"
                 : "=r"(r[0]), "=r"(r[1]), "=r"(r[2]), "=r"(r[3]) : "r"(addr));
}

__device__ __forceinline__ void mma_bf16(float* c, const uint32_t* a, const uint32_t* b)
{
    asm volatile(
        "mma.sync.aligned.m16n8k16.row.col.f32.bf16.bf16.f32 "
        "{%0,%1,%2,%3}, {%4,%5,%6,%7}, {%8,%9}, {%0,%1,%2,%3};"
        : "+f"(c[0]), "+f"(c[1]), "+f"(c[2]), "+f"(c[3])
        : "r"(a[0]), "r"(a[1]), "r"(a[2]), "r"(a[3]), "r"(b[0]), "r"(b[1]));
}

// =====================================================================
// bf16 split-precision warp-MMA GEMM:
//   C[M,N] = (Ahi+Alo)[M,K] * (Bhi+Blo)[N,K]^T + bias[N]   (lo*lo dropped)
// Block 128x128, 8 warps (2x4) of 64x32, K-chunk 64.
// Smem tiles: 128 rows x 128B (64 bf16), chunk-XOR swizzle (c ^= r&7).
// cp.async double buffer.  epi 0: fp32 out.  epi 1: GELU -> bf16 hi/lo out.
// M%128==0, N%128==0, K%64==0.
// =====================================================================
#define TEN  16384          // one 128x64 bf16 tile
#define STGB (4*TEN)        // Ahi,Alo,Bhi,Blo per stage

__global__ __launch_bounds__(256) void bgemm_kernel(
    const __nv_bfloat16* __restrict__ Ahi, const __nv_bfloat16* __restrict__ Alo, int lda,
    const __nv_bfloat16* __restrict__ Bhi, const __nv_bfloat16* __restrict__ Blo, int ldb,
    const float* __restrict__ bias,
    float* __restrict__ Cf,
    __nv_bfloat16* __restrict__ Chi, __nv_bfloat16* __restrict__ Clo,
    int ldc, int K, int epi)
{
    extern __shared__ char dsm[];
    const uint32_t sBase = smem_u32(dsm);

    const int tid  = threadIdx.x;
    const int warp = tid >> 5;
    const int lane = tid & 31;
    const int mBase = blockIdx.y << 7;
    const int nBase = blockIdx.x << 7;
    const int wm = (warp & 1) << 6;   // 0 / 64
    const int wn = (warp >> 1) << 5;  // 0 / 32 / 64 / 96

    // staging role: tensor = tid>>6 (0 Ahi, 1 Alo, 2 Bhi, 3 Blo)
    const int ten   = tid >> 6;
    const __nv_bfloat16* tp = (ten == 0) ? Ahi : (ten == 1) ? Alo : (ten == 2) ? Bhi : Blo;
    const int ldt   = (ten < 2) ? lda : ldb;
    const int rbase = (ten < 2) ? mBase : nBase;
    const int lsub  = tid & 63;

#define STAGE(kt) do {                                                         \
    uint32_t sdst = sBase + (((kt) & 1) ? STGB : 0) + ten * TEN;               \
    const __nv_bfloat16* gsrc = tp + (size_t)rbase * ldt + ((kt) << 6);        \
    _Pragma("unroll")                                                          \
    for (int q_ = 0; q_ < 16; q_++) {                                          \
        int id_  = lsub + (q_ << 6);                                           \
        int row_ = id_ >> 3;                                                   \
        int cc_  = id_ & 7;                                                    \
        uint32_t d_ = sdst + row_ * 128 + ((cc_ ^ (row_ & 7)) << 4);           \
        const __nv_bfloat16* s_ = gsrc + (size_t)row_ * ldt + (cc_ << 3);      \
        asm volatile("cp.async.cg.shared.global [%0], [%1], 16;"               \
                     :: "r"(d_), "l"(s_));                                     \
    }                                                                          \
} while (0)

    float acc[4][4][4];
#pragma unroll
    for (int mt = 0; mt < 4; mt++)
#pragma unroll
        for (int nt = 0; nt < 4; nt++)
#pragma unroll
            for (int c = 0; c < 4; c++) acc[mt][nt][c] = 0.f;

    const int nk = K >> 6;
    STAGE(0);
    asm volatile("cp.async.commit_group;");

    const int lane16 = lane & 15;
    const int lanehi = lane >> 4;
    const int brow_off = (lane & 7) + ((lane >> 4) << 3);  // B ldmatrix row within np-pair
    const int bchi     = (lane >> 3) & 1;                  // B k-chunk half

    for (int kt = 0; kt < nk; kt++) {
        if (kt + 1 < nk) STAGE(kt + 1);
        asm volatile("cp.async.commit_group;");
        asm volatile("cp.async.wait_group 1;");
        __syncthreads();

        const uint32_t buf = sBase + ((kt & 1) ? STGB : 0);
        const uint32_t sAh = buf, sAl = buf + TEN, sBh = buf + 2*TEN, sBl = buf + 3*TEN;

#pragma unroll
        for (int ks = 0; ks < 4; ks++) {
            uint32_t ah[4][4], al[4][4], bh[4][2], bl[4][2];
#pragma unroll
            for (int mt = 0; mt < 4; mt++) {
                int row = wm + mt*16 + lane16;
                uint32_t off = (uint32_t)(row * 128 + (((ks*2 + lanehi) ^ (row & 7)) << 4));
                ldsm4(ah[mt], sAh + off);
                ldsm4(al[mt], sAl + off);
            }
#pragma unroll
            for (int np = 0; np < 2; np++) {
                int row = wn + np*16 + brow_off;
                uint32_t off = (uint32_t)(row * 128 + (((ks*2 + bchi) ^ (row & 7)) << 4));
                uint32_t r4[4];
                ldsm4(r4, sBh + off);
                bh[np*2][0] = r4[0]; bh[np*2][1] = r4[1];
                bh[np*2+1][0] = r4[2]; bh[np*2+1][1] = r4[3];
                ldsm4(r4, sBl + off);
                bl[np*2][0] = r4[0]; bl[np*2][1] = r4[1];
                bl[np*2+1][0] = r4[2]; bl[np*2+1][1] = r4[3];
            }
#pragma unroll
            for (int mt = 0; mt < 4; mt++)
#pragma unroll
                for (int nt = 0; nt < 4; nt++) {
                    mma_bf16(acc[mt][nt], ah[mt], bh[nt]);
                    mma_bf16(acc[mt][nt], ah[mt], bl[nt]);
                    mma_bf16(acc[mt][nt], al[mt], bh[nt]);
                }
        }
        __syncthreads();
    }
#undef STAGE

    // epilogue: c-frag -> rows (wm+mt*16+g, +8), cols (wn+nt*8+2t)
    const int g = lane >> 2;
    const int t = lane & 3;
#pragma unroll
    for (int mt = 0; mt < 4; mt++) {
        int r0 = mBase + wm + mt*16 + g;
#pragma unroll
        for (int nt = 0; nt < 4; nt++) {
            int c0 = nBase + wn + nt*8 + 2*t;
            float b0 = __ldg(bias + c0);
            float b1 = __ldg(bias + c0 + 1);
            float v00 = acc[mt][nt][0] + b0;
            float v01 = acc[mt][nt][1] + b1;
            float v10 = acc[mt][nt][2] + b0;
            float v11 = acc[mt][nt][3] + b1;
            if (epi == 0) {
                *(float2*)(Cf + (size_t)r0 * ldc + c0)       = make_float2(v00, v01);
                *(float2*)(Cf + (size_t)(r0 + 8) * ldc + c0) = make_float2(v10, v11);
            } else {
                v00 = 0.5f * v00 * (1.0f + erff(v00 * 0.70710678118654752f));
                v01 = 0.5f * v01 * (1.0f + erff(v01 * 0.70710678118654752f));
                v10 = 0.5f * v10 * (1.0f + erff(v10 * 0.70710678118654752f));
                v11 = 0.5f * v11 * (1.0f + erff(v11 * 0.70710678118654752f));
                __nv_bfloat16 h00 = __float2bfloat16(v00);
                __nv_bfloat16 h01 = __float2bfloat16(v01);
                __nv_bfloat16 h10 = __float2bfloat16(v10);
                __nv_bfloat16 h11 = __float2bfloat16(v11);
                __nv_bfloat162 hi0; hi0.x = h00; hi0.y = h01;
                __nv_bfloat162 hi1; hi1.x = h10; hi1.y = h11;
                __nv_bfloat162 lo0; lo0.x = __float2bfloat16(v00 - __bfloat162float(h00));
                                    lo0.y = __float2bfloat16(v01 - __bfloat162float(h01));
                __nv_bfloat162 lo1; lo1.x = __float2bfloat16(v10 - __bfloat162float(h10));
                                    lo1.y = __float2bfloat16(v11 - __bfloat162float(h11));
                *(__nv_bfloat162*)(Chi + (size_t)r0 * ldc + c0)       = hi0;
                *(__nv_bfloat162*)(Chi + (size_t)(r0 + 8) * ldc + c0) = hi1;
                *(__nv_bfloat162*)(Clo + (size_t)r0 * ldc + c0)       = lo0;
                *(__nv_bfloat162*)(Clo + (size_t)(r0 + 8) * ldc + c0) = lo1;
            }
        }
    }
}

// =====================================================================
// fp32->bf16 hi/lo split
// =====================================================================
__global__ void split_kernel(const float4* __restrict__ src,
                             uint2* __restrict__ hi, uint2* __restrict__ lo, int n4)
{
    int i = blockIdx.x * blockDim.x + threadIdx.x;
    if (i >= n4) return;
    float4 v = src[i];
    __nv_bfloat16 h[4], l[4];
    h[0] = __float2bfloat16(v.x); l[0] = __float2bfloat16(v.x - __bfloat162float(h[0]));
    h[1] = __float2bfloat16(v.y); l[1] = __float2bfloat16(v.y - __bfloat162float(h[1]));
    h[2] = __float2bfloat16(v.z); l[2] = __float2bfloat16(v.z - __bfloat162float(h[2]));
    h[3] = __float2bfloat16(v.w); l[3] = __float2bfloat16(v.w - __bfloat162float(h[3]));
    hi[i] = *(uint2*)h;
    lo[i] = *(uint2*)l;
}

// =====================================================================
// fp32 tiled SGEMM (session alignment only)
// =====================================================================
#define BM 128
#define BN 64
#define BK 16

__global__ __launch_bounds__(256) void sgemm_kernel(
    const float* __restrict__ A, int lda,
    const float* __restrict__ Bm, int ldb,
    const float* __restrict__ bias,
    float* __restrict__ C, int ldc,
    int M, int N, int K,
    const int* __restrict__ sidx,
    size_t strideAb, size_t strideCb, size_t strideBsel, size_t strideBiasSel)
{
    __shared__ __align__(16) float As[BK][BM + 4];
    __shared__ __align__(16) float Bs[BK][BN + 4];

    if (sidx) {
        int bz = blockIdx.z;
        A    += (size_t)bz * strideAb;
        C    += (size_t)bz * strideCb;
        int s = __ldg(&sidx[bz]);
        Bm   += (size_t)s * strideBsel;
        bias += (size_t)s * strideBiasSel;
    }

    const int tid   = threadIdx.x;
    const int mBase = blockIdx.y * BM;
    const int nBase = blockIdx.x * BN;
    const int tm    = (tid / 16) * 8;
    const int tn    = (tid % 16) * 4;

    float acc[8][4];
#pragma unroll
    for (int i = 0; i < 8; i++)
#pragma unroll
        for (int j = 0; j < 4; j++) acc[i][j] = 0.f;

    for (int k0 = 0; k0 < K; k0 += BK) {
#pragma unroll
        for (int it = 0; it < 2; it++) {
            int l  = tid + it * 256;
            int m  = l >> 2;
            int kq = (l & 3) * 4;
            float4 v = *(const float4*)(A + (size_t)(mBase + m) * lda + k0 + kq);
            As[kq + 0][m] = v.x; As[kq + 1][m] = v.y;
            As[kq + 2][m] = v.z; As[kq + 3][m] = v.w;
        }
        {
            int l  = tid;
            int n  = l >> 2;
            int kq = (l & 3) * 4;
            float4 v = *(const float4*)(Bm + (size_t)(nBase + n) * ldb + k0 + kq);
            Bs[kq + 0][n] = v.x; Bs[kq + 1][n] = v.y;
            Bs[kq + 2][n] = v.z; Bs[kq + 3][n] = v.w;
        }
        __syncthreads();

#pragma unroll
        for (int kk = 0; kk < BK; kk++) {
            float4 a0 = *(const float4*)&As[kk][tm];
            float4 a1 = *(const float4*)&As[kk][tm + 4];
            float4 b0 = *(const float4*)&Bs[kk][tn];
            float av[8] = {a0.x, a0.y, a0.z, a0.w, a1.x, a1.y, a1.z, a1.w};
            float bv[4] = {b0.x, b0.y, b0.z, b0.w};
#pragma unroll
            for (int i = 0; i < 8; i++)
#pragma unroll
                for (int j = 0; j < 4; j++) acc[i][j] += av[i] * bv[j];
        }
        __syncthreads();
    }

    float bb[4];
#pragma unroll
    for (int j = 0; j < 4; j++) bb[j] = bias[nBase + tn + j];

#pragma unroll
    for (int i = 0; i < 8; i++) {
        *(float4*)(C + (size_t)(mBase + tm + i) * ldc + nBase + tn) =
            make_float4(acc[i][0] + bb[0], acc[i][1] + bb[1],
                        acc[i][2] + bb[2], acc[i][3] + bb[3]);
    }
}

// =====================================================================
// tokens gather
// =====================================================================
__global__ void tokens_kernel(float* __restrict__ out_tokens)
{
    int idx = blockIdx.x * blockDim.x + threadIdx.x;
    if (idx >= MROWS * TOK_) return;
    int t   = idx % TOK_;
    int row = idx / TOK_;
    int n   = row % N_;
    int b   = row / N_;
    int d   = t / P_;
    int p   = t % P_;
    out_tokens[idx] = g_aligned[((size_t)(b * T_ + n + p)) * D_ + d];
}

// =====================================================================
// RMS norm in place on g_h rows
// =====================================================================
__global__ __launch_bounds__(128) void rms_kernel(const float* __restrict__ scale)
{
    int row = blockIdx.x;
    float* h = g_h + (size_t)row * H_;
    int tid = threadIdx.x;

    float4 x = *(float4*)(h + tid * 4);
    float ss = x.x * x.x + x.y * x.y + x.z * x.z + x.w * x.w;
#pragma unroll
    for (int o = 16; o; o >>= 1) ss += __shfl_xor_sync(0xffffffffu, ss, o);

    __shared__ float wsum[4];
    if ((tid & 31) == 0) wsum[tid >> 5] = ss;
    __syncthreads();
    float tot = wsum[0] + wsum[1] + wsum[2] + wsum[3];
    float inv = rsqrtf(tot * (1.0f / H_) + 1e-6f);

    float4 sc = *(const float4*)(scale + tid * 4);
    x.x *= inv * sc.x; x.y *= inv * sc.y; x.z *= inv * sc.z; x.w *= inv * sc.w;
    *(float4*)(h + tid * 4) = x;
}

// =====================================================================
// GRU: persistent kernel (unchanged)
// =====================================================================
#define GRU_BLOCKS 128
#define CPB 4

__device__ __forceinline__ void grid_barrier(unsigned gen)
{
    __syncthreads();
    if (threadIdx.x == 0) {
        __threadfence();
        unsigned a = atomicAdd(&g_bar_arrive, 1u);
        if (a == gen * GRU_BLOCKS + (GRU_BLOCKS - 1)) {
            atomicAdd(&g_bar_release, 1u);
        } else {
            while (true) {
                unsigned r = *(volatile unsigned*)&g_bar_release;
                if (r > gen) break;
                __nanosleep(64);
            }
        }
        __threadfence();
    }
    __syncthreads();
}

__global__ void gru_init_kernel()
{
    int idx = blockIdx.x * blockDim.x + threadIdx.x;
    float* p = &g_hstateT[0][0][0];
    if (idx < 2 * H_ * B_) p[idx] = 0.f;
    if (idx == 0) { g_bar_arrive = 0u; g_bar_release = 0u; }
}

__global__ __launch_bounds__(256, 1) void gru_kernel(
    const float* __restrict__ Whh, const float* __restrict__ bhh)
{
    __shared__ __align__(16) float ws[H_][12];
    __shared__ float red[3][B_][12];
    __shared__ float sbhh[12];

    const int bid  = blockIdx.x;
    const int col0 = bid * CPB;
    const int tid  = threadIdx.x;

    for (int i = tid; i < H_ * 12; i += 256) {
        int k = i / 12, j = i % 12;
        int gg = j >> 2, c = j & 3;
        ws[k][j] = Whh[(size_t)(gg * H_ + col0 + c) * H_ + k];
    }
    if (tid < 12) {
        int gg = tid >> 2, c = tid & 3;
        sbhh[tid] = bhh[gg * H_ + col0 + c];
    }
    __syncthreads();

    const int b  = tid & 63;
    const int kq = tid >> 6;
    const int kb = kq * 128;
    int cur = 0;

    for (int n = 0; n < N_; n++) {
        float acc[12];
#pragma unroll
        for (int j = 0; j < 12; j++) acc[j] = 0.f;

        const float* hT = &g_hstateT[cur][0][0];
#pragma unroll 4
        for (int k = kb; k < kb + 128; k++) {
            float hv = __ldcg(hT + k * B_ + b);
            float4 w0 = *(const float4*)&ws[k][0];
            float4 w1 = *(const float4*)&ws[k][4];
            float4 w2 = *(const float4*)&ws[k][8];
            acc[0] += hv * w0.x; acc[1] += hv * w0.y; acc[2]  += hv * w0.z; acc[3]  += hv * w0.w;
            acc[4] += hv * w1.x; acc[5] += hv * w1.y; acc[6]  += hv * w1.z; acc[7]  += hv * w1.w;
            acc[8] += hv * w2.x; acc[9] += hv * w2.y; acc[10] += hv * w2.z; acc[11] += hv * w2.w;
        }

        if (kq) {
#pragma unroll
            for (int j = 0; j < 12; j++) red[kq - 1][b][j] = acc[j];
        }
        __syncthreads();

        if (kq == 0) {
            const float* gx = g_gx + ((size_t)(b * N_ + n)) * H3;
            float hn[4];
#pragma unroll
            for (int c = 0; c < 4; c++) {
                float ghr = acc[c]     + red[0][b][c]     + red[1][b][c]     + red[2][b][c]     + sbhh[c];
                float ghz = acc[4 + c] + red[0][b][4 + c] + red[1][b][4 + c] + red[2][b][4 + c] + sbhh[4 + c];
                float ghn = acc[8 + c] + red[0][b][8 + c] + red[1][b][8 + c] + red[2][b][8 + c] + sbhh[8 + c];
                float gxr = __ldg(gx + col0 + c);
                float gxz = __ldg(gx + H_ + col0 + c);
                float gxn = __ldg(gx + 2 * H_ + col0 + c);
                float r = 1.0f / (1.0f + expf(-(gxr + ghr)));
                float z = 1.0f / (1.0f + expf(-(gxz + ghz)));
                float nn = tanhf(gxn + r * ghn);
                float hp = __ldcg(&g_hstateT[cur][col0 + c][b]);
                hn[c] = (1.0f - z) * nn + z * hp;
                g_hstateT[cur ^ 1][col0 + c][b] = hn[c];
            }
            *(float4*)(g_hidden + ((size_t)(b * N_ + n)) * H_ + col0) =
                make_float4(hn[0], hn[1], hn[2], hn[3]);
        }

        grid_barrier((unsigned)n);
        cur ^= 1;
    }
}

// =====================================================================
// host side
// =====================================================================
#define BG_DSMEM (2 * STGB)   // 131072 B

static void launch_split(const float* src, __nv_bfloat16* hi, __nv_bfloat16* lo, size_t n)
{
    int n4 = (int)(n / 4);
    split_kernel<<<(n4 + 255) / 256, 256>>>((const float4*)src, (uint2*)hi, (uint2*)lo, n4);
}

extern "C" void kernel_launch(void* const* d_in, const int* in_sizes, int n_in,
                              void* d_out, int out_size)
{
    const float* x      = (const float*)d_in[0];
    const int*   sidx   = (const int*)  d_in[1];
    const float* sW     = (const float*)d_in[2];
    const float* sb     = (const float*)d_in[3];
    const float* projW  = (const float*)d_in[4];
    const float* projb  = (const float*)d_in[5];
    const float* rscale = (const float*)d_in[6];
    const float* Wih    = (const float*)d_in[7];
    const float* Whh    = (const float*)d_in[8];
    const float* bih    = (const float*)d_in[9];
    const float* bhh    = (const float*)d_in[10];
    const float* W1     = (const float*)d_in[11];
    const float* b1     = (const float*)d_in[12];
    const float* W2     = (const float*)d_in[13];
    const float* b2     = (const float*)d_in[14];

    float* out        = (float*)d_out;
    float* out_preds  = out;
    float* out_tokens = out + (size_t)K_H * MROWS * TOK_;

    float *pAligned, *pH, *pGx, *pHidden;
    cudaGetSymbolAddress((void**)&pAligned, g_aligned);
    cudaGetSymbolAddress((void**)&pH,       g_h);
    cudaGetSymbolAddress((void**)&pGx,      g_gx);
    cudaGetSymbolAddress((void**)&pHidden,  g_hidden);

    __nv_bfloat16 *tokHi, *tokLo, *hHi, *hLo, *hidHi, *hidLo, *actHi, *actLo;
    __nv_bfloat16 *pwHi, *pwLo, *wihHi, *wihLo, *w1Hi, *w1Lo, *w2Hi, *w2Lo;
    cudaGetSymbolAddress((void**)&tokHi, g_tokHi); cudaGetSymbolAddress((void**)&tokLo, g_tokLo);
    cudaGetSymbolAddress((void**)&hHi,   g_hHi);   cudaGetSymbolAddress((void**)&hLo,   g_hLo);
    cudaGetSymbolAddress((void**)&hidHi, g_hidHi); cudaGetSymbolAddress((void**)&hidLo, g_hidLo);
    cudaGetSymbolAddress((void**)&actHi, g_actHi); cudaGetSymbolAddress((void**)&actLo, g_actLo);
    cudaGetSymbolAddress((void**)&pwHi,  g_pwHi);  cudaGetSymbolAddress((void**)&pwLo,  g_pwLo);
    cudaGetSymbolAddress((void**)&wihHi, g_wihHi); cudaGetSymbolAddress((void**)&wihLo, g_wihLo);
    cudaGetSymbolAddress((void**)&w1Hi,  g_w1Hi);  cudaGetSymbolAddress((void**)&w1Lo,  g_w1Lo);
    cudaGetSymbolAddress((void**)&w2Hi,  g_w2Hi);  cudaGetSymbolAddress((void**)&w2Lo,  g_w2Lo);

    static int attr_set = 0;
    if (!attr_set) {
        cudaFuncSetAttribute(bgemm_kernel,
                             cudaFuncAttributeMaxDynamicSharedMemorySize, BG_DSMEM);
        attr_set = 1;
    }

    // 0) weight splits
    launch_split(projW, pwHi,  pwLo,  (size_t)H_ * TOK_);
    launch_split(Wih,   wihHi, wihLo, (size_t)H3 * H_);
    launch_split(W1,    w1Hi,  w1Lo,  (size_t)H3 * H_);
    launch_split(W2,    w2Hi,  w2Lo,  (size_t)K_H * TOK_ * H_);

    // 1) session alignment (fp32 — feeds tokens output)
    sgemm_kernel<<<dim3(D_ / BN, T_ / BM, B_), 256>>>(
        x, D_, sW, D_, sb, pAligned, D_,
        T_, D_, D_,
        sidx, (size_t)T_ * D_, (size_t)T_ * D_, (size_t)D_ * D_, (size_t)D_);

    // 2) tokens gather (second output) + split
    tokens_kernel<<<(MROWS * TOK_ + 255) / 256, 256>>>(out_tokens);
    launch_split(out_tokens, tokHi, tokLo, (size_t)MROWS * TOK_);

    // 3) proj: h = tokens @ projW^T + projb
    bgemm_kernel<<<dim3(H_ / 128, MROWS / 128), 256, BG_DSMEM>>>(
        tokHi, tokLo, TOK_, pwHi, pwLo, TOK_, projb,
        pH, nullptr, nullptr, H_, TOK_, 0);

    // 4) RMS norm in place + split
    rms_kernel<<<MROWS, 128>>>(rscale);
    launch_split(pH, hHi, hLo, (size_t)MROWS * H_);

    // 5) gx = h @ Wih^T + bih
    bgemm_kernel<<<dim3(H3 / 128, MROWS / 128), 256, BG_DSMEM>>>(
        hHi, hLo, H_, wihHi, wihLo, H_, bih,
        pGx, nullptr, nullptr, H3, H_, 0);

    // 6) GRU recurrence
    gru_init_kernel<<<(2 * H_ * B_ + 255) / 256, 256>>>();
    gru_kernel<<<GRU_BLOCKS, 256>>>(Whh, bhh);
    launch_split(pHidden, hidHi, hidLo, (size_t)MROWS * H_);

    // 7) head1 (3 horizons fused, N=1536) + exact GELU -> bf16 hi/lo
    bgemm_kernel<<<dim3(H3 / 128, MROWS / 128), 256, BG_DSMEM>>>(
        hidHi, hidLo, H_, w1Hi, w1Lo, H_, b1,
        nullptr, actHi, actLo, H3, H_, 1);

    // 8) head2 per horizon -> preds
    for (int k = 0; k < K_H; k++) {
        bgemm_kernel<<<dim3(TOK_ / 128, MROWS / 128), 256, BG_DSMEM>>>(
            actHi + (size_t)k * H_, actLo + (size_t)k * H_, H3,
            w2Hi + (size_t)k * TOK_ * H_, w2Lo + (size_t)k * TOK_ * H_, H_,
            b2 + (size_t)k * TOK_,
            out_preds + (size_t)k * MROWS * TOK_, nullptr, nullptr, TOK_, H_, 0);
    }
}

// round 5
// speedup vs baseline: 1.2929x; 1.0291x over previous
#include <cuda_runtime.h>
#include <cuda_bf16.h>
#include <math.h>
#include <stdint.h>

// ---------------- problem constants ----------------
#define B_   64
#define T_   512
#define D_   128
#define P_   3
#define H_   512
#define K_H  3
#define TOK_ 384
#define N_   510
#define MROWS (B_*N_)          // 32640
#define H3   (3*H_)            // 1536

// ---------------- device scratch ----------------
__device__ float g_aligned[B_*T_*D_];
__device__ float g_h[(size_t)MROWS*H_];
__device__ float g_gx[(size_t)MROWS*H3];
__device__ float g_hstateT[2][H_][B_];
__device__ unsigned g_flags[128*32];     // one 128B line per block
__device__ unsigned g_release;

// bf16 hi/lo split buffers
__device__ __nv_bfloat16 g_tokHi[(size_t)MROWS*TOK_];
__device__ __nv_bfloat16 g_tokLo[(size_t)MROWS*TOK_];
__device__ __nv_bfloat16 g_hHi[(size_t)MROWS*H_];
__device__ __nv_bfloat16 g_hLo[(size_t)MROWS*H_];
__device__ __nv_bfloat16 g_hidHi[(size_t)MROWS*H_];
__device__ __nv_bfloat16 g_hidLo[(size_t)MROWS*H_];
__device__ __nv_bfloat16 g_actHi[(size_t)MROWS*H3];
__device__ __nv_bfloat16 g_actLo[(size_t)MROWS*H3];
__device__ __nv_bfloat16 g_pwHi[H_*TOK_],  g_pwLo[H_*TOK_];
__device__ __nv_bfloat16 g_wihHi[H3*H_],   g_wihLo[H3*H_];
__device__ __nv_bfloat16 g_w1Hi[H3*H_],    g_w1Lo[H3*H_];
__device__ __nv_bfloat16 g_w2Hi[K_H*TOK_*H_], g_w2Lo[K_H*TOK_*H_];

// =====================================================================
// helpers
// =====================================================================
__device__ __forceinline__ uint32_t smem_u32(const void* p)
{
    uint32_t a;
    asm("{ .reg .u64 t; cvta.to.shared.u64 t, %1; cvt.u32.u64 %0, t; }"
        : "=r"(a) : "l"(p));
    return a;
}

__device__ __forceinline__ void ldsm4(uint32_t* r, uint32_t addr)
{
    asm volatile("ldmatrix.sync.aligned.m8n8.x4.shared.b16 {%0,%1,%2,%3}, [%4];"
                 : "=r"(r[0]), "=r"(r[1]), "=r"(r[2]), "=r"(r[3]) : "r"(addr));
}

__device__ __forceinline__ void mma_bf16(float* c, const uint32_t* a, const uint32_t* b)
{
    asm volatile(
        "mma.sync.aligned.m16n8k16.row.col.f32.bf16.bf16.f32 "
        "{%0,%1,%2,%3}, {%4,%5,%6,%7}, {%8,%9}, {%0,%1,%2,%3};"
        : "+f"(c[0]), "+f"(c[1]), "+f"(c[2]), "+f"(c[3])
        : "r"(a[0]), "r"(a[1]), "r"(a[2]), "r"(a[3]), "r"(b[0]), "r"(b[1]));
}

// packed f32x2 ops (PTX sm_100+)
typedef unsigned long long ull;
__device__ __forceinline__ ull pack2(float x, float y)
{
    ull r; asm("mov.b64 %0, {%1, %2};" : "=l"(r) : "f"(x), "f"(y)); return r;
}
__device__ __forceinline__ void unpack2(float& x, float& y, ull v)
{
    asm("mov.b64 {%0, %1}, %2;" : "=f"(x), "=f"(y) : "l"(v));
}
#define FMA2(d, a, b) asm("fma.rn.f32x2 %0, %1, %2, %0;" : "+l"(d) : "l"(a), "l"(b))
#define ADD2(d, a)    asm("add.rn.f32x2 %0, %0, %1;"     : "+l"(d) : "l"(a))

// =====================================================================
// bf16 split-precision warp-MMA GEMM (unchanged from R4 — proven correct)
// =====================================================================
#define TEN  16384
#define STGB (4*TEN)

__global__ __launch_bounds__(256) void bgemm_kernel(
    const __nv_bfloat16* __restrict__ Ahi, const __nv_bfloat16* __restrict__ Alo, int lda,
    const __nv_bfloat16* __restrict__ Bhi, const __nv_bfloat16* __restrict__ Blo, int ldb,
    const float* __restrict__ bias,
    float* __restrict__ Cf,
    __nv_bfloat16* __restrict__ Chi, __nv_bfloat16* __restrict__ Clo,
    int ldc, int K, int epi)
{
    extern __shared__ char dsm[];
    const uint32_t sBase = smem_u32(dsm);

    const int tid  = threadIdx.x;
    const int warp = tid >> 5;
    const int lane = tid & 31;
    const int mBase = blockIdx.y << 7;
    const int nBase = blockIdx.x << 7;
    const int wm = (warp & 1) << 6;
    const int wn = (warp >> 1) << 5;

    const int ten   = tid >> 6;
    const __nv_bfloat16* tp = (ten == 0) ? Ahi : (ten == 1) ? Alo : (ten == 2) ? Bhi : Blo;
    const int ldt   = (ten < 2) ? lda : ldb;
    const int rbase = (ten < 2) ? mBase : nBase;
    const int lsub  = tid & 63;

#define STAGE(kt) do {                                                         \
    uint32_t sdst = sBase + (((kt) & 1) ? STGB : 0) + ten * TEN;               \
    const __nv_bfloat16* gsrc = tp + (size_t)rbase * ldt + ((kt) << 6);        \
    _Pragma("unroll")                                                          \
    for (int q_ = 0; q_ < 16; q_++) {                                          \
        int id_  = lsub + (q_ << 6);                                           \
        int row_ = id_ >> 3;                                                   \
        int cc_  = id_ & 7;                                                    \
        uint32_t d_ = sdst + row_ * 128 + ((cc_ ^ (row_ & 7)) << 4);           \
        const __nv_bfloat16* s_ = gsrc + (size_t)row_ * ldt + (cc_ << 3);      \
        asm volatile("cp.async.cg.shared.global [%0], [%1], 16;"               \
                     :: "r"(d_), "l"(s_));                                     \
    }                                                                          \
} while (0)

    float acc[4][4][4];
#pragma unroll
    for (int mt = 0; mt < 4; mt++)
#pragma unroll
        for (int nt = 0; nt < 4; nt++)
#pragma unroll
            for (int c = 0; c < 4; c++) acc[mt][nt][c] = 0.f;

    const int nk = K >> 6;
    STAGE(0);
    asm volatile("cp.async.commit_group;");

    const int lane16 = lane & 15;
    const int lanehi = lane >> 4;
    const int brow_off = (lane & 7) + ((lane >> 4) << 3);
    const int bchi     = (lane >> 3) & 1;

    for (int kt = 0; kt < nk; kt++) {
        if (kt + 1 < nk) STAGE(kt + 1);
        asm volatile("cp.async.commit_group;");
        asm volatile("cp.async.wait_group 1;");
        __syncthreads();

        const uint32_t buf = sBase + ((kt & 1) ? STGB : 0);
        const uint32_t sAh = buf, sAl = buf + TEN, sBh = buf + 2*TEN, sBl = buf + 3*TEN;

#pragma unroll
        for (int ks = 0; ks < 4; ks++) {
            uint32_t ah[4][4], al[4][4], bh[4][2], bl[4][2];
#pragma unroll
            for (int mt = 0; mt < 4; mt++) {
                int row = wm + mt*16 + lane16;
                uint32_t off = (uint32_t)(row * 128 + (((ks*2 + lanehi) ^ (row & 7)) << 4));
                ldsm4(ah[mt], sAh + off);
                ldsm4(al[mt], sAl + off);
            }
#pragma unroll
            for (int np = 0; np < 2; np++) {
                int row = wn + np*16 + brow_off;
                uint32_t off = (uint32_t)(row * 128 + (((ks*2 + bchi) ^ (row & 7)) << 4));
                uint32_t r4[4];
                ldsm4(r4, sBh + off);
                bh[np*2][0] = r4[0]; bh[np*2][1] = r4[1];
                bh[np*2+1][0] = r4[2]; bh[np*2+1][1] = r4[3];
                ldsm4(r4, sBl + off);
                bl[np*2][0] = r4[0]; bl[np*2][1] = r4[1];
                bl[np*2+1][0] = r4[2]; bl[np*2+1][1] = r4[3];
            }
#pragma unroll
            for (int mt = 0; mt < 4; mt++)
#pragma unroll
                for (int nt = 0; nt < 4; nt++) {
                    mma_bf16(acc[mt][nt], ah[mt], bh[nt]);
                    mma_bf16(acc[mt][nt], ah[mt], bl[nt]);
                    mma_bf16(acc[mt][nt], al[mt], bh[nt]);
                }
        }
        __syncthreads();
    }
#undef STAGE

    const int g = lane >> 2;
    const int t = lane & 3;
#pragma unroll
    for (int mt = 0; mt < 4; mt++) {
        int r0 = mBase + wm + mt*16 + g;
#pragma unroll
        for (int nt = 0; nt < 4; nt++) {
            int c0 = nBase + wn + nt*8 + 2*t;
            float b0 = __ldg(bias + c0);
            float b1 = __ldg(bias + c0 + 1);
            float v00 = acc[mt][nt][0] + b0;
            float v01 = acc[mt][nt][1] + b1;
            float v10 = acc[mt][nt][2] + b0;
            float v11 = acc[mt][nt][3] + b1;
            if (epi == 0) {
                *(float2*)(Cf + (size_t)r0 * ldc + c0)       = make_float2(v00, v01);
                *(float2*)(Cf + (size_t)(r0 + 8) * ldc + c0) = make_float2(v10, v11);
            } else {
                v00 = 0.5f * v00 * (1.0f + erff(v00 * 0.70710678118654752f));
                v01 = 0.5f * v01 * (1.0f + erff(v01 * 0.70710678118654752f));
                v10 = 0.5f * v10 * (1.0f + erff(v10 * 0.70710678118654752f));
                v11 = 0.5f * v11 * (1.0f + erff(v11 * 0.70710678118654752f));
                __nv_bfloat16 h00 = __float2bfloat16(v00);
                __nv_bfloat16 h01 = __float2bfloat16(v01);
                __nv_bfloat16 h10 = __float2bfloat16(v10);
                __nv_bfloat16 h11 = __float2bfloat16(v11);
                __nv_bfloat162 hi0; hi0.x = h00; hi0.y = h01;
                __nv_bfloat162 hi1; hi1.x = h10; hi1.y = h11;
                __nv_bfloat162 lo0; lo0.x = __float2bfloat16(v00 - __bfloat162float(h00));
                                    lo0.y = __float2bfloat16(v01 - __bfloat162float(h01));
                __nv_bfloat162 lo1; lo1.x = __float2bfloat16(v10 - __bfloat162float(h10));
                                    lo1.y = __float2bfloat16(v11 - __bfloat162float(h11));
                *(__nv_bfloat162*)(Chi + (size_t)r0 * ldc + c0)       = hi0;
                *(__nv_bfloat162*)(Chi + (size_t)(r0 + 8) * ldc + c0) = hi1;
                *(__nv_bfloat162*)(Clo + (size_t)r0 * ldc + c0)       = lo0;
                *(__nv_bfloat162*)(Clo + (size_t)(r0 + 8) * ldc + c0) = lo1;
            }
        }
    }
}

// =====================================================================
// fp32->bf16 hi/lo split (weights only now)
// =====================================================================
__global__ void split_kernel(const float4* __restrict__ src,
                             uint2* __restrict__ hi, uint2* __restrict__ lo, int n4)
{
    int i = blockIdx.x * blockDim.x + threadIdx.x;
    if (i >= n4) return;
    float4 v = src[i];
    __nv_bfloat16 h[4], l[4];
    h[0] = __float2bfloat16(v.x); l[0] = __float2bfloat16(v.x - __bfloat162float(h[0]));
    h[1] = __float2bfloat16(v.y); l[1] = __float2bfloat16(v.y - __bfloat162float(h[1]));
    h[2] = __float2bfloat16(v.z); l[2] = __float2bfloat16(v.z - __bfloat162float(h[2]));
    h[3] = __float2bfloat16(v.w); l[3] = __float2bfloat16(v.w - __bfloat162float(h[3]));
    hi[i] = *(uint2*)h;
    lo[i] = *(uint2*)l;
}

// =====================================================================
// fp32 tiled SGEMM (session alignment only)
// =====================================================================
#define BM 128
#define BN 64
#define BK 16

__global__ __launch_bounds__(256) void sgemm_kernel(
    const float* __restrict__ A, int lda,
    const float* __restrict__ Bm, int ldb,
    const float* __restrict__ bias,
    float* __restrict__ C, int ldc,
    int M, int N, int K,
    const int* __restrict__ sidx,
    size_t strideAb, size_t strideCb, size_t strideBsel, size_t strideBiasSel)
{
    __shared__ __align__(16) float As[BK][BM + 4];
    __shared__ __align__(16) float Bs[BK][BN + 4];

    if (sidx) {
        int bz = blockIdx.z;
        A    += (size_t)bz * strideAb;
        C    += (size_t)bz * strideCb;
        int s = __ldg(&sidx[bz]);
        Bm   += (size_t)s * strideBsel;
        bias += (size_t)s * strideBiasSel;
    }

    const int tid   = threadIdx.x;
    const int mBase = blockIdx.y * BM;
    const int nBase = blockIdx.x * BN;
    const int tm    = (tid / 16) * 8;
    const int tn    = (tid % 16) * 4;

    float acc[8][4];
#pragma unroll
    for (int i = 0; i < 8; i++)
#pragma unroll
        for (int j = 0; j < 4; j++) acc[i][j] = 0.f;

    for (int k0 = 0; k0 < K; k0 += BK) {
#pragma unroll
        for (int it = 0; it < 2; it++) {
            int l  = tid + it * 256;
            int m  = l >> 2;
            int kq = (l & 3) * 4;
            float4 v = *(const float4*)(A + (size_t)(mBase + m) * lda + k0 + kq);
            As[kq + 0][m] = v.x; As[kq + 1][m] = v.y;
            As[kq + 2][m] = v.z; As[kq + 3][m] = v.w;
        }
        {
            int l  = tid;
            int n  = l >> 2;
            int kq = (l & 3) * 4;
            float4 v = *(const float4*)(Bm + (size_t)(nBase + n) * ldb + k0 + kq);
            Bs[kq + 0][n] = v.x; Bs[kq + 1][n] = v.y;
            Bs[kq + 2][n] = v.z; Bs[kq + 3][n] = v.w;
        }
        __syncthreads();

#pragma unroll
        for (int kk = 0; kk < BK; kk++) {
            float4 a0 = *(const float4*)&As[kk][tm];
            float4 a1 = *(const float4*)&As[kk][tm + 4];
            float4 b0 = *(const float4*)&Bs[kk][tn];
            float av[8] = {a0.x, a0.y, a0.z, a0.w, a1.x, a1.y, a1.z, a1.w};
            float bv[4] = {b0.x, b0.y, b0.z, b0.w};
#pragma unroll
            for (int i = 0; i < 8; i++)
#pragma unroll
                for (int j = 0; j < 4; j++) acc[i][j] += av[i] * bv[j];
        }
        __syncthreads();
    }

    float bb[4];
#pragma unroll
    for (int j = 0; j < 4; j++) bb[j] = bias[nBase + tn + j];

#pragma unroll
    for (int i = 0; i < 8; i++) {
        *(float4*)(C + (size_t)(mBase + tm + i) * ldc + nBase + tn) =
            make_float4(acc[i][0] + bb[0], acc[i][1] + bb[1],
                        acc[i][2] + bb[2], acc[i][3] + bb[3]);
    }
}

// =====================================================================
// tokens gather + bf16 hi/lo split fused
// =====================================================================
__global__ void tokens_split_kernel(float* __restrict__ out_tokens,
                                    __nv_bfloat16* __restrict__ tokHi,
                                    __nv_bfloat16* __restrict__ tokLo)
{
    int idx = blockIdx.x * blockDim.x + threadIdx.x;
    if (idx >= MROWS * TOK_) return;
    int t   = idx % TOK_;
    int row = idx / TOK_;
    int n   = row % N_;
    int b   = row / N_;
    int d   = t / P_;
    int p   = t % P_;
    float v = g_aligned[((size_t)(b * T_ + n + p)) * D_ + d];
    out_tokens[idx] = v;
    __nv_bfloat16 h = __float2bfloat16(v);
    tokHi[idx] = h;
    tokLo[idx] = __float2bfloat16(v - __bfloat162float(h));
}

// =====================================================================
// RMS norm + bf16 hi/lo split fused (reads g_h fp32, writes hHi/hLo)
// =====================================================================
__global__ __launch_bounds__(128) void rms_split_kernel(
    const float* __restrict__ scale,
    __nv_bfloat16* __restrict__ hHi, __nv_bfloat16* __restrict__ hLo)
{
    int row = blockIdx.x;
    const float* h = g_h + (size_t)row * H_;
    int tid = threadIdx.x;

    float4 x = *(const float4*)(h + tid * 4);
    float ss = x.x * x.x + x.y * x.y + x.z * x.z + x.w * x.w;
#pragma unroll
    for (int o = 16; o; o >>= 1) ss += __shfl_xor_sync(0xffffffffu, ss, o);

    __shared__ float wsum[4];
    if ((tid & 31) == 0) wsum[tid >> 5] = ss;
    __syncthreads();
    float tot = wsum[0] + wsum[1] + wsum[2] + wsum[3];
    float inv = rsqrtf(tot * (1.0f / H_) + 1e-6f);

    float4 sc = *(const float4*)(scale + tid * 4);
    float v[4] = { x.x * inv * sc.x, x.y * inv * sc.y,
                   x.z * inv * sc.z, x.w * inv * sc.w };
    __nv_bfloat16 hi[4], lo[4];
#pragma unroll
    for (int j = 0; j < 4; j++) {
        hi[j] = __float2bfloat16(v[j]);
        lo[j] = __float2bfloat16(v[j] - __bfloat162float(hi[j]));
    }
    *(uint2*)(hHi + (size_t)row * H_ + tid * 4) = *(uint2*)hi;
    *(uint2*)(hLo + (size_t)row * H_ + tid * 4) = *(uint2*)lo;
}

// =====================================================================
// GRU: persistent kernel, f32x2 packed FFMA, flag-array barrier,
// prefetched gx/h_prev, fused bf16 hi/lo hidden output.
// =====================================================================
#define GRU_BLOCKS 128
#define CPB 4

__global__ void gru_init_kernel()
{
    int idx = blockIdx.x * blockDim.x + threadIdx.x;
    float* p = &g_hstateT[0][0][0];
    if (idx < 2 * H_ * B_) p[idx] = 0.f;
    if (idx < 128 * 32) g_flags[idx] = 0u;
    if (idx == 0) g_release = 0u;
}

__device__ __forceinline__ void grid_barrier2(unsigned gen)
{
    __threadfence();
    __syncthreads();
    if (blockIdx.x == 0) {
        if (threadIdx.x > 0 && threadIdx.x < GRU_BLOCKS) {
            volatile unsigned* f = &g_flags[threadIdx.x * 32];
            while (*f < gen) { }
        }
        __syncthreads();
        if (threadIdx.x == 0) {
            __threadfence();
            *(volatile unsigned*)&g_release = gen;
        }
    } else {
        if (threadIdx.x == 0) {
            *(volatile unsigned*)&g_flags[blockIdx.x * 32] = gen;
            while (*(volatile unsigned*)&g_release < gen) __nanosleep(32);
        }
    }
    __syncthreads();
    __threadfence();
}

__global__ __launch_bounds__(256, 1) void gru_kernel(
    const float* __restrict__ Whh, const float* __restrict__ bhh,
    __nv_bfloat16* __restrict__ hidHi, __nv_bfloat16* __restrict__ hidLo)
{
    __shared__ __align__(16) ull ws2[H_][6];     // packed col-pairs, 24KB
    __shared__ __align__(16) ull red2[3][B_][6]; // 9KB
    __shared__ float sbhh[12];

    const int bid  = blockIdx.x;
    const int col0 = bid * CPB;
    const int tid  = threadIdx.x;

    // fill ws: float layout [k][j] identical to packed [k][j/2]
    float* wsf = (float*)&ws2[0][0];
    for (int i = tid; i < H_ * 12; i += 256) {
        int k = i / 12, j = i % 12;
        int gg = j >> 2, c = j & 3;
        wsf[k * 12 + j] = Whh[(size_t)(gg * H_ + col0 + c) * H_ + k];
    }
    if (tid < 12) {
        int gg = tid >> 2, c = tid & 3;
        sbhh[tid] = bhh[gg * H_ + col0 + c];
    }
    __syncthreads();

    const int b  = tid & 63;
    const int kq = tid >> 6;
    const int kb = kq * 128;
    int cur = 0;

    for (int n = 0; n < N_; n++) {
        // prefetch gx + previous own-state (kq==0 threads only use them)
        float gxv[12], hp[4];
        if (kq == 0) {
            const float* gx = g_gx + ((size_t)(b * N_ + n)) * H3;
#pragma unroll
            for (int c = 0; c < 4; c++) {
                gxv[c]     = __ldg(gx + col0 + c);
                gxv[4 + c] = __ldg(gx + H_ + col0 + c);
                gxv[8 + c] = __ldg(gx + 2 * H_ + col0 + c);
                hp[c]      = __ldcg(&g_hstateT[cur][col0 + c][b]);
            }
        }

        ull acc2[6];
#pragma unroll
        for (int j = 0; j < 6; j++) acc2[j] = pack2(0.f, 0.f);

        const float* hT = &g_hstateT[cur][0][0];
#pragma unroll 4
        for (int k = kb; k < kb + 128; k++) {
            float hv = __ldcg(hT + k * B_ + b);
            ull hv2 = pack2(hv, hv);
            ulonglong2 w01 = *(const ulonglong2*)&ws2[k][0];
            ulonglong2 w23 = *(const ulonglong2*)&ws2[k][2];
            ulonglong2 w45 = *(const ulonglong2*)&ws2[k][4];
            FMA2(acc2[0], hv2, w01.x);
            FMA2(acc2[1], hv2, w01.y);
            FMA2(acc2[2], hv2, w23.x);
            FMA2(acc2[3], hv2, w23.y);
            FMA2(acc2[4], hv2, w45.x);
            FMA2(acc2[5], hv2, w45.y);
        }

        if (kq) {
            ulonglong2* r = (ulonglong2*)&red2[kq - 1][b][0];
            r[0] = make_ulonglong2(acc2[0], acc2[1]);
            r[1] = make_ulonglong2(acc2[2], acc2[3]);
            r[2] = make_ulonglong2(acc2[4], acc2[5]);
        }
        __syncthreads();

        if (kq == 0) {
#pragma unroll
            for (int i = 0; i < 3; i++) {
                const ull* r = &red2[i][b][0];
#pragma unroll
                for (int j = 0; j < 6; j++) ADD2(acc2[j], r[j]);
            }
            float gh[12];
#pragma unroll
            for (int j = 0; j < 6; j++) unpack2(gh[2*j], gh[2*j + 1], acc2[j]);

            __nv_bfloat16 oh[4], ol[4];
            float hn[4];
#pragma unroll
            for (int c = 0; c < 4; c++) {
                float ghr = gh[c]     + sbhh[c];
                float ghz = gh[4 + c] + sbhh[4 + c];
                float ghn = gh[8 + c] + sbhh[8 + c];
                float r = 1.0f / (1.0f + expf(-(gxv[c] + ghr)));
                float z = 1.0f / (1.0f + expf(-(gxv[4 + c] + ghz)));
                float nn = tanhf(gxv[8 + c] + r * ghn);
                hn[c] = (1.0f - z) * nn + z * hp[c];
                g_hstateT[cur ^ 1][col0 + c][b] = hn[c];
                oh[c] = __float2bfloat16(hn[c]);
                ol[c] = __float2bfloat16(hn[c] - __bfloat162float(oh[c]));
            }
            size_t base = ((size_t)(b * N_ + n)) * H_ + col0;
            *(uint2*)(hidHi + base) = *(uint2*)oh;
            *(uint2*)(hidLo + base) = *(uint2*)ol;
        }

        grid_barrier2((unsigned)(n + 1));
        cur ^= 1;
    }
}

// =====================================================================
// host side
// =====================================================================
#define BG_DSMEM (2 * STGB)   // 131072 B

static void launch_split(const float* src, __nv_bfloat16* hi, __nv_bfloat16* lo, size_t n)
{
    int n4 = (int)(n / 4);
    split_kernel<<<(n4 + 255) / 256, 256>>>((const float4*)src, (uint2*)hi, (uint2*)lo, n4);
}

extern "C" void kernel_launch(void* const* d_in, const int* in_sizes, int n_in,
                              void* d_out, int out_size)
{
    const float* x      = (const float*)d_in[0];
    const int*   sidx   = (const int*)  d_in[1];
    const float* sW     = (const float*)d_in[2];
    const float* sb     = (const float*)d_in[3];
    const float* projW  = (const float*)d_in[4];
    const float* projb  = (const float*)d_in[5];
    const float* rscale = (const float*)d_in[6];
    const float* Wih    = (const float*)d_in[7];
    const float* Whh    = (const float*)d_in[8];
    const float* bih    = (const float*)d_in[9];
    const float* bhh    = (const float*)d_in[10];
    const float* W1     = (const float*)d_in[11];
    const float* b1     = (const float*)d_in[12];
    const float* W2     = (const float*)d_in[13];
    const float* b2     = (const float*)d_in[14];

    float* out        = (float*)d_out;
    float* out_preds  = out;
    float* out_tokens = out + (size_t)K_H * MROWS * TOK_;

    float *pAligned, *pH, *pGx;
    cudaGetSymbolAddress((void**)&pAligned, g_aligned);
    cudaGetSymbolAddress((void**)&pH,       g_h);
    cudaGetSymbolAddress((void**)&pGx,      g_gx);

    __nv_bfloat16 *tokHi, *tokLo, *hHi, *hLo, *hidHi, *hidLo, *actHi, *actLo;
    __nv_bfloat16 *pwHi, *pwLo, *wihHi, *wihLo, *w1Hi, *w1Lo, *w2Hi, *w2Lo;
    cudaGetSymbolAddress((void**)&tokHi, g_tokHi); cudaGetSymbolAddress((void**)&tokLo, g_tokLo);
    cudaGetSymbolAddress((void**)&hHi,   g_hHi);   cudaGetSymbolAddress((void**)&hLo,   g_hLo);
    cudaGetSymbolAddress((void**)&hidHi, g_hidHi); cudaGetSymbolAddress((void**)&hidLo, g_hidLo);
    cudaGetSymbolAddress((void**)&actHi, g_actHi); cudaGetSymbolAddress((void**)&actLo, g_actLo);
    cudaGetSymbolAddress((void**)&pwHi,  g_pwHi);  cudaGetSymbolAddress((void**)&pwLo,  g_pwLo);
    cudaGetSymbolAddress((void**)&wihHi, g_wihHi); cudaGetSymbolAddress((void**)&wihLo, g_wihLo);
    cudaGetSymbolAddress((void**)&w1Hi,  g_w1Hi);  cudaGetSymbolAddress((void**)&w1Lo,  g_w1Lo);
    cudaGetSymbolAddress((void**)&w2Hi,  g_w2Hi);  cudaGetSymbolAddress((void**)&w2Lo,  g_w2Lo);

    static int attr_set = 0;
    if (!attr_set) {
        cudaFuncSetAttribute(bgemm_kernel,
                             cudaFuncAttributeMaxDynamicSharedMemorySize, BG_DSMEM);
        attr_set = 1;
    }

    // 0) proj weight split (first — so the profiled slot lands on bgemm)
    launch_split(projW, pwHi, pwLo, (size_t)H_ * TOK_);

    // 1) session alignment (fp32 — feeds tokens output)
    sgemm_kernel<<<dim3(D_ / BN, T_ / BM, B_), 256>>>(
        x, D_, sW, D_, sb, pAligned, D_,
        T_, D_, D_,
        sidx, (size_t)T_ * D_, (size_t)T_ * D_, (size_t)D_ * D_, (size_t)D_);

    // 2) tokens gather + split (fused)
    tokens_split_kernel<<<(MROWS * TOK_ + 255) / 256, 256>>>(out_tokens, tokHi, tokLo);

    // 3) proj GEMM  <-- profiled launch slot
    bgemm_kernel<<<dim3(H_ / 128, MROWS / 128), 256, BG_DSMEM>>>(
        tokHi, tokLo, TOK_, pwHi, pwLo, TOK_, projb,
        pH, nullptr, nullptr, H_, TOK_, 0);

    // 4) RMS + split (fused)
    rms_split_kernel<<<MROWS, 128>>>(rscale, hHi, hLo);

    // 5) remaining weight splits
    launch_split(Wih, wihHi, wihLo, (size_t)H3 * H_);

    // 6) gx = h @ Wih^T + bih
    bgemm_kernel<<<dim3(H3 / 128, MROWS / 128), 256, BG_DSMEM>>>(
        hHi, hLo, H_, wihHi, wihLo, H_, bih,
        pGx, nullptr, nullptr, H3, H_, 0);

    launch_split(W1, w1Hi, w1Lo, (size_t)H3 * H_);
    launch_split(W2, w2Hi, w2Lo, (size_t)K_H * TOK_ * H_);

    // 7) GRU recurrence (writes bf16 hi/lo hidden directly)
    gru_init_kernel<<<(2 * H_ * B_ + 255) / 256, 256>>>();
    gru_kernel<<<GRU_BLOCKS, 256>>>(Whh, bhh, hidHi, hidLo);

    // 8) head1 (3 horizons fused, N=1536) + exact GELU -> bf16 hi/lo
    bgemm_kernel<<<dim3(H3 / 128, MROWS / 128), 256, BG_DSMEM>>>(
        hidHi, hidLo, H_, w1Hi, w1Lo, H_, b1,
        nullptr, actHi, actLo, H3, H_, 1);

    // 9) head2 per horizon -> preds
    for (int k = 0; k < K_H; k++) {
        bgemm_kernel<<<dim3(TOK_ / 128, MROWS / 128), 256, BG_DSMEM>>>(
            actHi + (size_t)k * H_, actLo + (size_t)k * H_, H3,
            w2Hi + (size_t)k * TOK_ * H_, w2Lo + (size_t)k * TOK_ * H_, H_,
            b2 + (size_t)k * TOK_,
            out_preds + (size_t)k * MROWS * TOK_, nullptr, nullptr, TOK_, H_, 0);
    }
}

// round 6
// speedup vs baseline: 1.8949x; 1.4656x over previous
#include <cuda_runtime.h>
#include <cuda_bf16.h>
#include <math.h>
#include <stdint.h>

// ---------------- problem constants ----------------
#define B_   64
#define T_   512
#define D_   128
#define P_   3
#define H_   512
#define K_H  3
#define TOK_ 384
#define N_   510
#define MROWS (B_*N_)          // 32640
#define H3   (3*H_)            // 1536

// ---------------- device scratch ----------------
__device__ float g_aligned[B_*T_*D_];
__device__ float g_h[(size_t)MROWS*H_];
__device__ float g_gx[(size_t)MROWS*H3];
__device__ float g_hstate[2][B_][H_];     // b-major GRU state, double buffered
__device__ unsigned g_ctr;

// bf16 hi/lo split buffers
__device__ __nv_bfloat16 g_tokHi[(size_t)MROWS*TOK_];
__device__ __nv_bfloat16 g_tokLo[(size_t)MROWS*TOK_];
__device__ __nv_bfloat16 g_hHi[(size_t)MROWS*H_];
__device__ __nv_bfloat16 g_hLo[(size_t)MROWS*H_];
__device__ __nv_bfloat16 g_hidHi[(size_t)MROWS*H_];
__device__ __nv_bfloat16 g_hidLo[(size_t)MROWS*H_];
__device__ __nv_bfloat16 g_actHi[(size_t)MROWS*H3];
__device__ __nv_bfloat16 g_actLo[(size_t)MROWS*H3];
__device__ __nv_bfloat16 g_pwHi[H_*TOK_],  g_pwLo[H_*TOK_];
__device__ __nv_bfloat16 g_wihHi[H3*H_],   g_wihLo[H3*H_];
__device__ __nv_bfloat16 g_w1Hi[H3*H_],    g_w1Lo[H3*H_];
__device__ __nv_bfloat16 g_w2Hi[K_H*TOK_*H_], g_w2Lo[K_H*TOK_*H_];

// =====================================================================
// helpers
// =====================================================================
__device__ __forceinline__ uint32_t smem_u32(const void* p)
{
    uint32_t a;
    asm("{ .reg .u64 t; cvta.to.shared.u64 t, %1; cvt.u32.u64 %0, t; }"
        : "=r"(a) : "l"(p));
    return a;
}

__device__ __forceinline__ void ldsm4(uint32_t* r, uint32_t addr)
{
    asm volatile("ldmatrix.sync.aligned.m8n8.x4.shared.b16 {%0,%1,%2,%3}, [%4];"
                 : "=r"(r[0]), "=r"(r[1]), "=r"(r[2]), "=r"(r[3]) : "r"(addr));
}

__device__ __forceinline__ void mma_bf16(float* c, const uint32_t* a, const uint32_t* b)
{
    asm volatile(
        "mma.sync.aligned.m16n8k16.row.col.f32.bf16.bf16.f32 "
        "{%0,%1,%2,%3}, {%4,%5,%6,%7}, {%8,%9}, {%0,%1,%2,%3};"
        : "+f"(c[0]), "+f"(c[1]), "+f"(c[2]), "+f"(c[3])
        : "r"(a[0]), "r"(a[1]), "r"(a[2]), "r"(a[3]), "r"(b[0]), "r"(b[1]));
}

// packed f32x2 ops
typedef unsigned long long ull;
__device__ __forceinline__ ull pack2(float x, float y)
{
    ull r; asm("mov.b64 %0, {%1, %2};" : "=l"(r) : "f"(x), "f"(y)); return r;
}
__device__ __forceinline__ void unpack2(float& x, float& y, ull v)
{
    asm("mov.b64 {%0, %1}, %2;" : "=f"(x), "=f"(y) : "l"(v));
}
#define FMA2(d, a, b) asm("fma.rn.f32x2 %0, %1, %2, %0;" : "+l"(d) : "l"(a), "l"(b))

// =====================================================================
// bf16 split-precision warp-MMA GEMM (unchanged — proven, 59% tensor)
// =====================================================================
#define TEN  16384
#define STGB (4*TEN)

__global__ __launch_bounds__(256) void bgemm_kernel(
    const __nv_bfloat16* __restrict__ Ahi, const __nv_bfloat16* __restrict__ Alo, int lda,
    const __nv_bfloat16* __restrict__ Bhi, const __nv_bfloat16* __restrict__ Blo, int ldb,
    const float* __restrict__ bias,
    float* __restrict__ Cf,
    __nv_bfloat16* __restrict__ Chi, __nv_bfloat16* __restrict__ Clo,
    int ldc, int K, int epi)
{
    extern __shared__ char dsm[];
    const uint32_t sBase = smem_u32(dsm);

    const int tid  = threadIdx.x;
    const int warp = tid >> 5;
    const int lane = tid & 31;
    const int mBase = blockIdx.y << 7;
    const int nBase = blockIdx.x << 7;
    const int wm = (warp & 1) << 6;
    const int wn = (warp >> 1) << 5;

    const int ten   = tid >> 6;
    const __nv_bfloat16* tp = (ten == 0) ? Ahi : (ten == 1) ? Alo : (ten == 2) ? Bhi : Blo;
    const int ldt   = (ten < 2) ? lda : ldb;
    const int rbase = (ten < 2) ? mBase : nBase;
    const int lsub  = tid & 63;

#define STAGE(kt) do {                                                         \
    uint32_t sdst = sBase + (((kt) & 1) ? STGB : 0) + ten * TEN;               \
    const __nv_bfloat16* gsrc = tp + (size_t)rbase * ldt + ((kt) << 6);        \
    _Pragma("unroll")                                                          \
    for (int q_ = 0; q_ < 16; q_++) {                                          \
        int id_  = lsub + (q_ << 6);                                           \
        int row_ = id_ >> 3;                                                   \
        int cc_  = id_ & 7;                                                    \
        uint32_t d_ = sdst + row_ * 128 + ((cc_ ^ (row_ & 7)) << 4);           \
        const __nv_bfloat16* s_ = gsrc + (size_t)row_ * ldt + (cc_ << 3);      \
        asm volatile("cp.async.cg.shared.global [%0], [%1], 16;"               \
                     :: "r"(d_), "l"(s_));                                     \
    }                                                                          \
} while (0)

    float acc[4][4][4];
#pragma unroll
    for (int mt = 0; mt < 4; mt++)
#pragma unroll
        for (int nt = 0; nt < 4; nt++)
#pragma unroll
            for (int c = 0; c < 4; c++) acc[mt][nt][c] = 0.f;

    const int nk = K >> 6;
    STAGE(0);
    asm volatile("cp.async.commit_group;");

    const int lane16 = lane & 15;
    const int lanehi = lane >> 4;
    const int brow_off = (lane & 7) + ((lane >> 4) << 3);
    const int bchi     = (lane >> 3) & 1;

    for (int kt = 0; kt < nk; kt++) {
        if (kt + 1 < nk) STAGE(kt + 1);
        asm volatile("cp.async.commit_group;");
        asm volatile("cp.async.wait_group 1;");
        __syncthreads();

        const uint32_t buf = sBase + ((kt & 1) ? STGB : 0);
        const uint32_t sAh = buf, sAl = buf + TEN, sBh = buf + 2*TEN, sBl = buf + 3*TEN;

#pragma unroll
        for (int ks = 0; ks < 4; ks++) {
            uint32_t ah[4][4], al[4][4], bh[4][2], bl[4][2];
#pragma unroll
            for (int mt = 0; mt < 4; mt++) {
                int row = wm + mt*16 + lane16;
                uint32_t off = (uint32_t)(row * 128 + (((ks*2 + lanehi) ^ (row & 7)) << 4));
                ldsm4(ah[mt], sAh + off);
                ldsm4(al[mt], sAl + off);
            }
#pragma unroll
            for (int np = 0; np < 2; np++) {
                int row = wn + np*16 + brow_off;
                uint32_t off = (uint32_t)(row * 128 + (((ks*2 + bchi) ^ (row & 7)) << 4));
                uint32_t r4[4];
                ldsm4(r4, sBh + off);
                bh[np*2][0] = r4[0]; bh[np*2][1] = r4[1];
                bh[np*2+1][0] = r4[2]; bh[np*2+1][1] = r4[3];
                ldsm4(r4, sBl + off);
                bl[np*2][0] = r4[0]; bl[np*2][1] = r4[1];
                bl[np*2+1][0] = r4[2]; bl[np*2+1][1] = r4[3];
            }
#pragma unroll
            for (int mt = 0; mt < 4; mt++)
#pragma unroll
                for (int nt = 0; nt < 4; nt++) {
                    mma_bf16(acc[mt][nt], ah[mt], bh[nt]);
                    mma_bf16(acc[mt][nt], ah[mt], bl[nt]);
                    mma_bf16(acc[mt][nt], al[mt], bh[nt]);
                }
        }
        __syncthreads();
    }
#undef STAGE

    const int g = lane >> 2;
    const int t = lane & 3;
#pragma unroll
    for (int mt = 0; mt < 4; mt++) {
        int r0 = mBase + wm + mt*16 + g;
#pragma unroll
        for (int nt = 0; nt < 4; nt++) {
            int c0 = nBase + wn + nt*8 + 2*t;
            float b0 = __ldg(bias + c0);
            float b1 = __ldg(bias + c0 + 1);
            float v00 = acc[mt][nt][0] + b0;
            float v01 = acc[mt][nt][1] + b1;
            float v10 = acc[mt][nt][2] + b0;
            float v11 = acc[mt][nt][3] + b1;
            if (epi == 0) {
                *(float2*)(Cf + (size_t)r0 * ldc + c0)       = make_float2(v00, v01);
                *(float2*)(Cf + (size_t)(r0 + 8) * ldc + c0) = make_float2(v10, v11);
            } else {
                v00 = 0.5f * v00 * (1.0f + erff(v00 * 0.70710678118654752f));
                v01 = 0.5f * v01 * (1.0f + erff(v01 * 0.70710678118654752f));
                v10 = 0.5f * v10 * (1.0f + erff(v10 * 0.70710678118654752f));
                v11 = 0.5f * v11 * (1.0f + erff(v11 * 0.70710678118654752f));
                __nv_bfloat16 h00 = __float2bfloat16(v00);
                __nv_bfloat16 h01 = __float2bfloat16(v01);
                __nv_bfloat16 h10 = __float2bfloat16(v10);
                __nv_bfloat16 h11 = __float2bfloat16(v11);
                __nv_bfloat162 hi0; hi0.x = h00; hi0.y = h01;
                __nv_bfloat162 hi1; hi1.x = h10; hi1.y = h11;
                __nv_bfloat162 lo0; lo0.x = __float2bfloat16(v00 - __bfloat162float(h00));
                                    lo0.y = __float2bfloat16(v01 - __bfloat162float(h01));
                __nv_bfloat162 lo1; lo1.x = __float2bfloat16(v10 - __bfloat162float(h10));
                                    lo1.y = __float2bfloat16(v11 - __bfloat162float(h11));
                *(__nv_bfloat162*)(Chi + (size_t)r0 * ldc + c0)       = hi0;
                *(__nv_bfloat162*)(Chi + (size_t)(r0 + 8) * ldc + c0) = hi1;
                *(__nv_bfloat162*)(Clo + (size_t)r0 * ldc + c0)       = lo0;
                *(__nv_bfloat162*)(Clo + (size_t)(r0 + 8) * ldc + c0) = lo1;
            }
        }
    }
}

// =====================================================================
// fp32->bf16 hi/lo split (weights)
// =====================================================================
__global__ void split_kernel(const float4* __restrict__ src,
                             uint2* __restrict__ hi, uint2* __restrict__ lo, int n4)
{
    int i = blockIdx.x * blockDim.x + threadIdx.x;
    if (i >= n4) return;
    float4 v = src[i];
    __nv_bfloat16 h[4], l[4];
    h[0] = __float2bfloat16(v.x); l[0] = __float2bfloat16(v.x - __bfloat162float(h[0]));
    h[1] = __float2bfloat16(v.y); l[1] = __float2bfloat16(v.y - __bfloat162float(h[1]));
    h[2] = __float2bfloat16(v.z); l[2] = __float2bfloat16(v.z - __bfloat162float(h[2]));
    h[3] = __float2bfloat16(v.w); l[3] = __float2bfloat16(v.w - __bfloat162float(h[3]));
    hi[i] = *(uint2*)h;
    lo[i] = *(uint2*)l;
}

// =====================================================================
// fp32 tiled SGEMM (session alignment only)
// =====================================================================
#define BM 128
#define BN 64
#define BK 16

__global__ __launch_bounds__(256) void sgemm_kernel(
    const float* __restrict__ A, int lda,
    const float* __restrict__ Bm, int ldb,
    const float* __restrict__ bias,
    float* __restrict__ C, int ldc,
    int M, int N, int K,
    const int* __restrict__ sidx,
    size_t strideAb, size_t strideCb, size_t strideBsel, size_t strideBiasSel)
{
    __shared__ __align__(16) float As[BK][BM + 4];
    __shared__ __align__(16) float Bs[BK][BN + 4];

    if (sidx) {
        int bz = blockIdx.z;
        A    += (size_t)bz * strideAb;
        C    += (size_t)bz * strideCb;
        int s = __ldg(&sidx[bz]);
        Bm   += (size_t)s * strideBsel;
        bias += (size_t)s * strideBiasSel;
    }

    const int tid   = threadIdx.x;
    const int mBase = blockIdx.y * BM;
    const int nBase = blockIdx.x * BN;
    const int tm    = (tid / 16) * 8;
    const int tn    = (tid % 16) * 4;

    float acc[8][4];
#pragma unroll
    for (int i = 0; i < 8; i++)
#pragma unroll
        for (int j = 0; j < 4; j++) acc[i][j] = 0.f;

    for (int k0 = 0; k0 < K; k0 += BK) {
#pragma unroll
        for (int it = 0; it < 2; it++) {
            int l  = tid + it * 256;
            int m  = l >> 2;
            int kq = (l & 3) * 4;
            float4 v = *(const float4*)(A + (size_t)(mBase + m) * lda + k0 + kq);
            As[kq + 0][m] = v.x; As[kq + 1][m] = v.y;
            As[kq + 2][m] = v.z; As[kq + 3][m] = v.w;
        }
        {
            int l  = tid;
            int n  = l >> 2;
            int kq = (l & 3) * 4;
            float4 v = *(const float4*)(Bm + (size_t)(nBase + n) * ldb + k0 + kq);
            Bs[kq + 0][n] = v.x; Bs[kq + 1][n] = v.y;
            Bs[kq + 2][n] = v.z; Bs[kq + 3][n] = v.w;
        }
        __syncthreads();

#pragma unroll
        for (int kk = 0; kk < BK; kk++) {
            float4 a0 = *(const float4*)&As[kk][tm];
            float4 a1 = *(const float4*)&As[kk][tm + 4];
            float4 b0 = *(const float4*)&Bs[kk][tn];
            float av[8] = {a0.x, a0.y, a0.z, a0.w, a1.x, a1.y, a1.z, a1.w};
            float bv[4] = {b0.x, b0.y, b0.z, b0.w};
#pragma unroll
            for (int i = 0; i < 8; i++)
#pragma unroll
                for (int j = 0; j < 4; j++) acc[i][j] += av[i] * bv[j];
        }
        __syncthreads();
    }

    float bb[4];
#pragma unroll
    for (int j = 0; j < 4; j++) bb[j] = bias[nBase + tn + j];

#pragma unroll
    for (int i = 0; i < 8; i++) {
        *(float4*)(C + (size_t)(mBase + tm + i) * ldc + nBase + tn) =
            make_float4(acc[i][0] + bb[0], acc[i][1] + bb[1],
                        acc[i][2] + bb[2], acc[i][3] + bb[3]);
    }
}

// =====================================================================
// tokens gather + bf16 hi/lo split fused
// =====================================================================
__global__ void tokens_split_kernel(float* __restrict__ out_tokens,
                                    __nv_bfloat16* __restrict__ tokHi,
                                    __nv_bfloat16* __restrict__ tokLo)
{
    int idx = blockIdx.x * blockDim.x + threadIdx.x;
    if (idx >= MROWS * TOK_) return;
    int t   = idx % TOK_;
    int row = idx / TOK_;
    int n   = row % N_;
    int b   = row / N_;
    int d   = t / P_;
    int p   = t % P_;
    float v = g_aligned[((size_t)(b * T_ + n + p)) * D_ + d];
    out_tokens[idx] = v;
    __nv_bfloat16 h = __float2bfloat16(v);
    tokHi[idx] = h;
    tokLo[idx] = __float2bfloat16(v - __bfloat162float(h));
}

// =====================================================================
// RMS norm + bf16 hi/lo split fused
// =====================================================================
__global__ __launch_bounds__(128) void rms_split_kernel(
    const float* __restrict__ scale,
    __nv_bfloat16* __restrict__ hHi, __nv_bfloat16* __restrict__ hLo)
{
    int row = blockIdx.x;
    const float* h = g_h + (size_t)row * H_;
    int tid = threadIdx.x;

    float4 x = *(const float4*)(h + tid * 4);
    float ss = x.x * x.x + x.y * x.y + x.z * x.z + x.w * x.w;
#pragma unroll
    for (int o = 16; o; o >>= 1) ss += __shfl_xor_sync(0xffffffffu, ss, o);

    __shared__ float wsum[4];
    if ((tid & 31) == 0) wsum[tid >> 5] = ss;
    __syncthreads();
    float tot = wsum[0] + wsum[1] + wsum[2] + wsum[3];
    float inv = rsqrtf(tot * (1.0f / H_) + 1e-6f);

    float4 sc = *(const float4*)(scale + tid * 4);
    float v[4] = { x.x * inv * sc.x, x.y * inv * sc.y,
                   x.z * inv * sc.z, x.w * inv * sc.w };
    __nv_bfloat16 hi[4], lo[4];
#pragma unroll
    for (int j = 0; j < 4; j++) {
        hi[j] = __float2bfloat16(v[j]);
        lo[j] = __float2bfloat16(v[j] - __bfloat162float(hi[j]));
    }
    *(uint2*)(hHi + (size_t)row * H_ + tid * 4) = *(uint2*)hi;
    *(uint2*)(hLo + (size_t)row * H_ + tid * 4) = *(uint2*)lo;
}

// =====================================================================
// GRU v2: 128 blocks = 32 col-groups (16 cols) x 4 batch-groups (16 b).
// Weights (48 rows x 512 k, packed f32x2 col-pairs) resident in smem.
// h-state slice (16 b x 512 k) staged to smem per step via cp.async.
// 256 threads: k-phase (lb=tid&15, kq=tid>>4, k-range 32),
//              out-phase (oc=tid&15, ob=tid>>4) -> one h_new per thread.
// One-hop global barrier: REDG arrive + acquire poll.
// =====================================================================
#define GRU_BLOCKS 128
#define HSH_LD 516   // padded row stride (floats): 516 % 128 -> bank-shift 1

__global__ void gru_init_kernel()
{
    int idx = blockIdx.x * blockDim.x + threadIdx.x;
    float* p = &g_hstate[0][0][0];
    if (idx < 2 * B_ * H_) p[idx] = 0.f;
    if (idx == 0) g_ctr = 0u;
}

__device__ __forceinline__ void gbar(unsigned target)
{
    __threadfence();
    __syncthreads();
    if (threadIdx.x == 0) {
        atomicAdd(&g_ctr, 1u);
        unsigned v;
        do {
            asm volatile("ld.acquire.gpu.u32 %0, [%1];" : "=r"(v) : "l"(&g_ctr));
        } while (v < target);
    }
    __syncthreads();
}

__global__ __launch_bounds__(256, 1) void gru_kernel(
    const float* __restrict__ Whh, const float* __restrict__ bhh,
    __nv_bfloat16* __restrict__ hidHi, __nv_bfloat16* __restrict__ hidLo)
{
    extern __shared__ char gsm[];
    ull*   ws2  = (ull*)gsm;                       // [512*24]   98304 B
    ull*   red  = ws2 + 512*24;                    // [16*16*24] 49152 B
    float* hsh  = (float*)(red + 16*16*24);        // [16*HSH_LD] 33024 B
    float* sbhh = hsh + 16*HSH_LD;                 // [48]

    const int bid  = blockIdx.x;
    const int cg   = bid >> 2;        // 0..31
    const int bg   = bid & 3;         // 0..3
    const int tid  = threadIdx.x;
    const int col0 = cg * 16;

    // one-time: weights packed as col-pairs, k-major
    for (int i = tid; i < 512*24; i += 256) {
        int k = i / 24, j = i % 24;
        int g  = j >> 3;
        int cp = (j & 7) << 1;
        float w0 = Whh[(size_t)(g*H_ + col0 + cp)     * H_ + k];
        float w1 = Whh[(size_t)(g*H_ + col0 + cp + 1) * H_ + k];
        ws2[i] = pack2(w0, w1);
    }
    if (tid < 48) {
        int g = tid >> 4, c = tid & 15;
        sbhh[tid] = bhh[g*H_ + col0 + c];
    }
    __syncthreads();

    const int lb  = tid & 15;        // k-phase batch (local)
    const int kq  = tid >> 4;        // k-phase k-group (0..15)
    const int oc  = tid & 15;        // out-phase column (local)
    const int ob  = tid >> 4;        // out-phase batch (local)
    const int gbo = bg * 16 + ob;
    const int ocol = col0 + oc;

    int cur = 0;
    for (int n = 0; n < N_; n++) {
        // prefetch gx for this thread's output (hidden under staging+matvec)
        const float* gx = g_gx + ((size_t)(gbo * N_ + n)) * H3;
        float gxr = __ldg(gx + ocol);
        float gxz = __ldg(gx + H_ + ocol);
        float gxn = __ldg(gx + 2*H_ + ocol);

        // stage h slice (16 b x 512) coalesced into smem
#pragma unroll
        for (int q = 0; q < 8; q++) {
            int fi  = tid * 8 + q;          // float4 index in [0,2048)
            int bb  = fi >> 7;              // row (128 float4 per row)
            int kk4 = fi & 127;
            uint32_t dst = smem_u32(&hsh[bb * HSH_LD + kk4 * 4]);
            const float* src = &g_hstate[cur][bg*16 + bb][kk4 * 4];
            asm volatile("cp.async.ca.shared.global [%0], [%1], 16;"
                         :: "r"(dst), "l"(src));
        }
        asm volatile("cp.async.commit_group;");
        asm volatile("cp.async.wait_group 0;");
        __syncthreads();

        // matvec partials: 48 rows x 32 k per thread
        ull acc2[24];
#pragma unroll
        for (int j = 0; j < 24; j++) acc2[j] = 0ull;

        const float* hr = &hsh[lb * HSH_LD + kq * 32];
        const ull*   wb = &ws2[(kq * 32) * 24];
#pragma unroll 8
        for (int kk = 0; kk < 32; kk++) {
            float hv = hr[kk];
            ull h2 = pack2(hv, hv);
            const ulonglong2* w = (const ulonglong2*)(wb + kk * 24);
#pragma unroll
            for (int jj = 0; jj < 12; jj++) {
                ulonglong2 wv = w[jj];
                FMA2(acc2[2*jj],     h2, wv.x);
                FMA2(acc2[2*jj + 1], h2, wv.y);
            }
        }

        {
            ulonglong2* rp = (ulonglong2*)&red[(size_t)(kq * 16 + lb) * 24];
#pragma unroll
            for (int jj = 0; jj < 12; jj++)
                rp[jj] = make_ulonglong2(acc2[2*jj], acc2[2*jj + 1]);
        }
        float hp = hsh[ob * HSH_LD + ocol];   // previous state for output
        __syncthreads();

        // reduce 16 kq partials -> gates -> h_new (one output per thread)
        const float* rf = (const float*)red;   // [kq][b][48]
        float s0 = 0.f, s1 = 0.f, s2 = 0.f;
#pragma unroll
        for (int q = 0; q < 16; q++) {
            const float* r = rf + (size_t)(q * 16 + ob) * 48;
            s0 += r[oc];
            s1 += r[16 + oc];
            s2 += r[32 + oc];
        }
        float r  = 1.0f / (1.0f + expf(-(gxr + s0 + sbhh[oc])));
        float z  = 1.0f / (1.0f + expf(-(gxz + s1 + sbhh[16 + oc])));
        float nn = tanhf(gxn + r * (s2 + sbhh[32 + oc]));
        float hn = (1.0f - z) * nn + z * hp;

        g_hstate[cur ^ 1][gbo][ocol] = hn;
        __nv_bfloat16 oh = __float2bfloat16(hn);
        size_t base = ((size_t)(gbo * N_ + n)) * H_ + ocol;
        hidHi[base] = oh;
        hidLo[base] = __float2bfloat16(hn - __bfloat162float(oh));

        gbar((unsigned)(n + 1) * GRU_BLOCKS);
        cur ^= 1;
    }
}

// =====================================================================
// host side
// =====================================================================
#define BG_DSMEM  (2 * STGB)                                   // 131072 B
#define GRU_DSMEM (512*24*8 + 16*16*24*8 + 16*HSH_LD*4 + 48*4) // 180672 B

static void launch_split(const float* src, __nv_bfloat16* hi, __nv_bfloat16* lo, size_t n)
{
    int n4 = (int)(n / 4);
    split_kernel<<<(n4 + 255) / 256, 256>>>((const float4*)src, (uint2*)hi, (uint2*)lo, n4);
}

extern "C" void kernel_launch(void* const* d_in, const int* in_sizes, int n_in,
                              void* d_out, int out_size)
{
    const float* x      = (const float*)d_in[0];
    const int*   sidx   = (const int*)  d_in[1];
    const float* sW     = (const float*)d_in[2];
    const float* sb     = (const float*)d_in[3];
    const float* projW  = (const float*)d_in[4];
    const float* projb  = (const float*)d_in[5];
    const float* rscale = (const float*)d_in[6];
    const float* Wih    = (const float*)d_in[7];
    const float* Whh    = (const float*)d_in[8];
    const float* bih    = (const float*)d_in[9];
    const float* bhh    = (const float*)d_in[10];
    const float* W1     = (const float*)d_in[11];
    const float* b1     = (const float*)d_in[12];
    const float* W2     = (const float*)d_in[13];
    const float* b2     = (const float*)d_in[14];

    float* out        = (float*)d_out;
    float* out_preds  = out;
    float* out_tokens = out + (size_t)K_H * MROWS * TOK_;

    float *pAligned, *pH, *pGx;
    cudaGetSymbolAddress((void**)&pAligned, g_aligned);
    cudaGetSymbolAddress((void**)&pH,       g_h);
    cudaGetSymbolAddress((void**)&pGx,      g_gx);

    __nv_bfloat16 *tokHi, *tokLo, *hHi, *hLo, *hidHi, *hidLo, *actHi, *actLo;
    __nv_bfloat16 *pwHi, *pwLo, *wihHi, *wihLo, *w1Hi, *w1Lo, *w2Hi, *w2Lo;
    cudaGetSymbolAddress((void**)&tokHi, g_tokHi); cudaGetSymbolAddress((void**)&tokLo, g_tokLo);
    cudaGetSymbolAddress((void**)&hHi,   g_hHi);   cudaGetSymbolAddress((void**)&hLo,   g_hLo);
    cudaGetSymbolAddress((void**)&hidHi, g_hidHi); cudaGetSymbolAddress((void**)&hidLo, g_hidLo);
    cudaGetSymbolAddress((void**)&actHi, g_actHi); cudaGetSymbolAddress((void**)&actLo, g_actLo);
    cudaGetSymbolAddress((void**)&pwHi,  g_pwHi);  cudaGetSymbolAddress((void**)&pwLo,  g_pwLo);
    cudaGetSymbolAddress((void**)&wihHi, g_wihHi); cudaGetSymbolAddress((void**)&wihLo, g_wihLo);
    cudaGetSymbolAddress((void**)&w1Hi,  g_w1Hi);  cudaGetSymbolAddress((void**)&w1Lo,  g_w1Lo);
    cudaGetSymbolAddress((void**)&w2Hi,  g_w2Hi);  cudaGetSymbolAddress((void**)&w2Lo,  g_w2Lo);

    static int attr_set = 0;
    if (!attr_set) {
        cudaFuncSetAttribute(bgemm_kernel,
                             cudaFuncAttributeMaxDynamicSharedMemorySize, BG_DSMEM);
        cudaFuncSetAttribute(gru_kernel,
                             cudaFuncAttributeMaxDynamicSharedMemorySize, GRU_DSMEM);
        attr_set = 1;
    }

    // 0) proj weight split
    launch_split(projW, pwHi, pwLo, (size_t)H_ * TOK_);

    // 1) session alignment (fp32 — feeds tokens output)
    sgemm_kernel<<<dim3(D_ / BN, T_ / BM, B_), 256>>>(
        x, D_, sW, D_, sb, pAligned, D_,
        T_, D_, D_,
        sidx, (size_t)T_ * D_, (size_t)T_ * D_, (size_t)D_ * D_, (size_t)D_);

    // 2) tokens gather + split (fused)
    tokens_split_kernel<<<(MROWS * TOK_ + 255) / 256, 256>>>(out_tokens, tokHi, tokLo);

    // 3) proj GEMM
    bgemm_kernel<<<dim3(H_ / 128, MROWS / 128), 256, BG_DSMEM>>>(
        tokHi, tokLo, TOK_, pwHi, pwLo, TOK_, projb,
        pH, nullptr, nullptr, H_, TOK_, 0);

    // 4) RMS + split (fused)
    rms_split_kernel<<<MROWS, 128>>>(rscale, hHi, hLo);

    // 5) Wih split
    launch_split(Wih, wihHi, wihLo, (size_t)H3 * H_);

    // 6) gx = h @ Wih^T + bih
    bgemm_kernel<<<dim3(H3 / 128, MROWS / 128), 256, BG_DSMEM>>>(
        hHi, hLo, H_, wihHi, wihLo, H_, bih,
        pGx, nullptr, nullptr, H3, H_, 0);

    launch_split(W1, w1Hi, w1Lo, (size_t)H3 * H_);
    launch_split(W2, w2Hi, w2Lo, (size_t)K_H * TOK_ * H_);

    // 7) GRU recurrence (bf16 hi/lo hidden out)
    gru_init_kernel<<<(2 * B_ * H_ + 255) / 256, 256>>>();
    gru_kernel<<<GRU_BLOCKS, 256, GRU_DSMEM>>>(Whh, bhh, hidHi, hidLo);

    // 8) head1 (3 horizons fused, N=1536) + exact GELU -> bf16 hi/lo
    bgemm_kernel<<<dim3(H3 / 128, MROWS / 128), 256, BG_DSMEM>>>(
        hidHi, hidLo, H_, w1Hi, w1Lo, H_, b1,
        nullptr, actHi, actLo, H3, H_, 1);

    // 9) head2 per horizon -> preds
    for (int k = 0; k < K_H; k++) {
        bgemm_kernel<<<dim3(TOK_ / 128, MROWS / 128), 256, BG_DSMEM>>>(
            actHi + (size_t)k * H_, actLo + (size_t)k * H_, H3,
            w2Hi + (size_t)k * TOK_ * H_, w2Lo + (size_t)k * TOK_ * H_, H_,
            b2 + (size_t)k * TOK_,
            out_preds + (size_t)k * MROWS * TOK_, nullptr, nullptr, TOK_, H_, 0);
    }
}